// round 12
// baseline (speedup 1.0000x reference)
#include <cuda_runtime.h>
#include <cuda_fp16.h>
#include <cstdint>
#include <math.h>

#define Bdim 16
#define Tdim 1024
#define Cdim 512
#define Kma  25
#define NWv  4
#define Mrows (Bdim*Tdim)
#define SEG  16
#define SEGLEN (Tdim/SEG)   // 64

// ===================== scratch ==============================================
__device__ __half g_Ac16[Mrows*3*Cdim];
__device__ __half g_sA16[Mrows*Cdim];
__device__ __half g_Aa16[Mrows*Cdim];
__device__ __half g_s16 [Mrows*Cdim];
__device__ __half g_a16 [Mrows*Cdim];
__device__ float  g_bias0[Cdim];
__device__ float  g_Spart[SEG][Bdim*Cdim];
__device__ float  g_tr0[Bdim*Cdim];
__device__ float  g_trN[Bdim*Cdim];
__device__ float  g_hacc[Bdim*Cdim];
__device__ float  g_wp [Bdim*2*NWv];
__device__ __half g_Wc16[Cdim*3*Cdim];
__device__ __half g_Ww16[Cdim*NWv*Cdim];
__device__ __half g_Wa16[Cdim*Cdim];

// ===================== helpers ==============================================
__device__ __forceinline__ uint32_t smem_u32(const void* p) {
    uint32_t a;
    asm("{ .reg .u64 t; cvta.to.shared.u64 t, %1; cvt.u32.u64 %0, t; }" : "=r"(a) : "l"(p));
    return a;
}
__device__ __forceinline__ void cp16(uint32_t dst, const void* src) {
    asm volatile("cp.async.cg.shared.global [%0], [%1], 16;" :: "r"(dst), "l"(src));
}
__device__ __forceinline__ void cp_commit() { asm volatile("cp.async.commit_group;"); }
template<int N> __device__ __forceinline__ void cp_wait() {
    asm volatile("cp.async.wait_group %0;" :: "n"(N));
}
__device__ __forceinline__ void ldmx4(uint32_t addr, uint32_t* r) {
    asm volatile("ldmatrix.sync.aligned.m8n8.x4.shared.b16 {%0,%1,%2,%3}, [%4];"
        : "=r"(r[0]), "=r"(r[1]), "=r"(r[2]), "=r"(r[3]) : "r"(addr));
}
__device__ __forceinline__ void mma16816(float* c, const uint32_t* a, const uint32_t* b) {
    asm volatile("mma.sync.aligned.m16n8k16.row.col.f32.f16.f16.f32 "
        "{%0,%1,%2,%3}, {%4,%5,%6,%7}, {%8,%9}, {%0,%1,%2,%3};"
        : "+f"(c[0]), "+f"(c[1]), "+f"(c[2]), "+f"(c[3])
        : "r"(a[0]), "r"(a[1]), "r"(a[2]), "r"(a[3]), "r"(b[0]), "r"(b[1]));
}
__device__ __forceinline__ uint32_t hmul2u(uint32_t a, uint32_t b) {
    __half2 r = __hmul2(*reinterpret_cast<__half2*>(&a), *reinterpret_cast<__half2*>(&b));
    return *reinterpret_cast<uint32_t*>(&r);
}

// ===================== K0: fused weight prep ================================
__global__ void prep_all(const float* __restrict__ cheby,
                         const float* __restrict__ wav_w,
                         const float* __restrict__ amp_w) {
    int bx = blockIdx.x;
    int tx = threadIdx.x & 31, ty = threadIdx.x >> 5;

    if (bx == 2048) {
        for (int o = threadIdx.x; o < Cdim; o += 256) {
            float s = 0.f;
            for (int c = 0; c < Cdim; ++c) s += cheby[(c*Cdim + o)*4];
            g_bias0[o] = s;
        }
        return;
    }

    const float* src; __half* dst; int Ktot, kb, ob, mode;
    if (bx < 768)       { mode = 0; src = cheby; dst = g_Wc16; Ktot = 3*Cdim;
                          kb = (bx % 48)*32;  ob = (bx / 48)*32; }
    else if (bx < 1792) { mode = 1; src = wav_w; dst = g_Ww16; Ktot = NWv*Cdim;
                          int i = bx - 768;  kb = (i % 64)*32; ob = (i / 64)*32; }
    else                { mode = 2; src = amp_w; dst = g_Wa16; Ktot = Cdim;
                          int i = bx - 1792; kb = (i % 16)*32; ob = (i / 16)*32; }

    __shared__ float tile[32][33];
    #pragma unroll
    for (int s = 0; s < 32; s += 8) {
        int k = kb + ty + s, o = ob + tx;
        float v;
        if (mode == 0) { int d = k >> 9, c = k & 511; v = src[(c*Cdim + o)*4 + d + 1]; }
        else           { v = src[(size_t)k*Cdim + o]; }
        tile[ty+s][tx] = v;
    }
    __syncthreads();
    #pragma unroll
    for (int s = 0; s < 32; s += 8) {
        int o = ob + ty + s, k = kb + tx;
        dst[(size_t)o*Ktot + k] = __float2half_rn(tile[tx][ty+s]);
    }
}

// ===================== K1: decomposition (2 ch/thread, SEG=16) ==============
__global__ void decomp_kernel(const float* __restrict__ x,
                              const float* __restrict__ tw, const float* __restrict__ tb,
                              const float* __restrict__ sw, const float* __restrict__ sb) {
    int idx = blockIdx.x*blockDim.x + threadIdx.x;      // 65536 threads
    int c2  = idx & 255;
    int c0  = c2*2;
    int tmp = idx >> 8;
    int b   = tmp & (Bdim-1);
    int seg = tmp >> 4;
    const float2* xb = reinterpret_cast<const float2*>(x + (size_t)b*Tdim*Cdim) + c2;
    const float inv = 1.0f/(float)Kma;

    float w0tx=tw[c0*3+0], w1tx=tw[c0*3+1], w2tx=tw[c0*3+2], btcx=tb[c0];
    float w0ty=tw[c0*3+3], w1ty=tw[c0*3+4], w2ty=tw[c0*3+5], btcy=tb[c0+1];
    float w0sx=sw[c0*3+0], w1sx=sw[c0*3+1], w2sx=sw[c0*3+2], bscx=sb[c0];
    float w0sy=sw[c0*3+3], w1sy=sw[c0*3+4], w2sy=sw[c0*3+5], bscy=sb[c0+1];

    int t0 = seg*SEGLEN, t1 = t0 + SEGLEN;
    float2 ws = make_float2(0.f, 0.f);
    int tref = (seg==0) ? 0 : (t0-1);
    #pragma unroll 5
    for (int j = tref-(Kma-1); j <= tref; ++j) {
        float2 v = xb[max(j,0)*256];
        ws.x += v.x; ws.y += v.y;
    }

    float2 tr_m1, tr_c, x_m1, x_c;
    if (seg == 0) {
        tr_c = make_float2(ws.x*inv, ws.y*inv); tr_m1 = tr_c;
        x_c  = xb[0];  x_m1 = x_c;
    } else {
        tr_m1 = make_float2(ws.x*inv, ws.y*inv);
        x_m1  = xb[(t0-1)*256];
        float2 vin = xb[t0*256], vout = xb[max(t0-Kma,0)*256];
        ws.x += vin.x - vout.x; ws.y += vin.y - vout.y;
        tr_c  = make_float2(ws.x*inv, ws.y*inv);
        x_c   = vin;
    }

    float2 Ssum = make_float2(0.f, 0.f);
    for (int t = t0; t < t1; ++t) {
        Ssum.x += tr_c.x; Ssum.y += tr_c.y;
        float2 tr_p, x_p;
        if (t+1 < Tdim) {
            x_p = xb[(t+1)*256];
            float2 vout = xb[max(t+1-Kma,0)*256];
            ws.x += x_p.x - vout.x; ws.y += x_p.y - vout.y;
            tr_p = make_float2(ws.x*inv, ws.y*inv);
        } else { x_p = x_c; tr_p = tr_c; }

        int m = b*Tdim + t;
        float tctxx = fmaf(tr_m1.x,w0tx, fmaf(tr_c.x,w1tx, fmaf(tr_p.x,w2tx, btcx)));
        float tctxy = fmaf(tr_m1.y,w0ty, fmaf(tr_c.y,w1ty, fmaf(tr_p.y,w2ty, btcy)));
        float xtx = tanhf(tctxx), xty = tanhf(tctxy);
        float d2x = fmaf(2.f*xtx, xtx, -1.f), d2y = fmaf(2.f*xty, xty, -1.f);
        float d3x = xtx * fmaf(4.f*xtx, xtx, -3.f), d3y = xty * fmaf(4.f*xty, xty, -3.f);
        size_t arow = (size_t)m*(3*Cdim) + c0;
        *reinterpret_cast<__half2*>(&g_Ac16[arow])          = __floats2half2_rn(xtx, xty);
        *reinterpret_cast<__half2*>(&g_Ac16[arow + Cdim])   = __floats2half2_rn(d2x, d2y);
        *reinterpret_cast<__half2*>(&g_Ac16[arow + 2*Cdim]) = __floats2half2_rn(d3x, d3y);

        float sm1x = x_m1.x-tr_m1.x, scx = x_c.x-tr_c.x, sppx = x_p.x-tr_p.x;
        float sm1y = x_m1.y-tr_m1.y, scy = x_c.y-tr_c.y, sppy = x_p.y-tr_p.y;
        float sctxx = fmaf(sm1x,w0sx, fmaf(scx,w1sx, fmaf(sppx,w2sx, bscx)));
        float sctxy = fmaf(sm1y,w0sy, fmaf(scy,w1sy, fmaf(sppy,w2sy, bscy)));
        *reinterpret_cast<__half2*>(&g_sA16[(size_t)m*Cdim + c0]) = __floats2half2_rn(sctxx, sctxy);

        if (t == 0)      *reinterpret_cast<float2*>(&g_tr0[b*Cdim+c0]) = tr_c;
        if (t == Tdim-1) *reinterpret_cast<float2*>(&g_trN[b*Cdim+c0]) = tr_c;
        tr_m1 = tr_c; tr_c = tr_p; x_m1 = x_c; x_c = x_p;
    }
    *reinterpret_cast<float2*>(&g_Spart[seg][b*Cdim+c0]) = Ssum;
}

// ===================== K2: hypernetwork (3 kernels) =========================
__global__ void hyper_pool(const float* __restrict__ slw, const float* __restrict__ slb) {
    int b = blockIdx.x, c = threadIdx.x;   // 16 x 512
    g_hacc[b*Cdim + c] = 0.f;
    float S = 0.f;
    #pragma unroll
    for (int s = 0; s < SEG; ++s) S += g_Spart[s][b*Cdim+c];
    float tr0 = g_tr0[b*Cdim+c], trN = g_trN[b*Cdim+c];
    float a0 = slw[c*3+0], a1 = slw[c*3+1], a2 = slw[c*3+2];
    float sp = (a0*(S + tr0 - trN) + a1*S + a2*(S - tr0 + trN)) * (1.0f/Tdim) + slb[c];
    __syncthreads();
    g_Spart[0][b*Cdim + c] = sp;
    g_Spart[1][b*Cdim + c] = S * (1.0f/Tdim);
}

__global__ void hyper_mm(const float* __restrict__ w1) {
    int b = blockIdx.y, ks = blockIdx.z;
    int col = blockIdx.x*128 + (threadIdx.x & 127);
    int kh  = threadIdx.x >> 7;
    __shared__ float hs[128];
    if (threadIdx.x < 128) {
        int hidx = ks*128 + threadIdx.x;
        hs[threadIdx.x] = (hidx < Cdim) ? g_Spart[0][b*Cdim + hidx]
                                        : g_Spart[1][b*Cdim + (hidx - Cdim)];
    }
    __syncthreads();
    const float* wp = w1 + (size_t)(ks*128 + kh*64)*Cdim + col;
    const float* hp = hs + kh*64;
    float a0=0.f, a1=0.f, a2=0.f, a3=0.f;
    #pragma unroll 4
    for (int i = 0; i < 64; i += 4) {
        a0 = fmaf(hp[i+0], wp[(i+0)*Cdim], a0);
        a1 = fmaf(hp[i+1], wp[(i+1)*Cdim], a1);
        a2 = fmaf(hp[i+2], wp[(i+2)*Cdim], a2);
        a3 = fmaf(hp[i+3], wp[(i+3)*Cdim], a3);
    }
    atomicAdd(&g_hacc[b*Cdim + col], (a0+a1)+(a2+a3));
}

__global__ void hyper_psi(const float* __restrict__ w2, const float* __restrict__ b2,
                          const float* __restrict__ b1) {
    int b = blockIdx.x;
    int j = threadIdx.x;                      // 256
    int warp = j >> 5, lane = j & 31;
    __shared__ float params_s[2*NWv];
    if (warp < 2*NWv) {
        float v = 0.f;
        for (int jj = lane; jj < Cdim; jj += 32) {
            float hv = g_hacc[b*Cdim + jj] + b1[jj];
            hv = hv / (1.f + expf(-hv));
            v = fmaf(hv, w2[jj*(2*NWv) + warp], v);
        }
        #pragma unroll
        for (int o = 16; o; o >>= 1) v += __shfl_down_sync(0xffffffffu, v, o);
        if (lane == 0) params_s[warp] = v + b2[warp];
    }
    __syncthreads();
    if (j < NWv) {
        float a = params_s[j*2+0], bb = params_s[j*2+1];
        g_wp[b*2*NWv + j*2 + 0] = ((a > 20.f) ? a : log1pf(expf(a))) + 0.01f;
        g_wp[b*2*NWv + j*2 + 1] = (float)Tdim / (1.f + expf(-bb));
    }
}

// ===================== fp16 mma GEMM (128x64 tile, 3 CTA/SM) ================
// warp grid 2(m) x 4(n); warp tile 64x16; 32 accumulators/thread.
#define SPADH 40
#define TO_B  (128*SPADH*2)                 // 10240 B (A tile)
#define STG_BYTES (TO_B + 64*SPADH*2)       // 15360 B (A 128 + B 64 rows)
#define NSTAGE 4
#define SMEM_GEMM (NSTAGE*STG_BYTES)        // 61440 B; 3 CTAs = 184320

__global__ __launch_bounds__(256, 3)
void gemm_kernel(int modeBase, const float* __restrict__ ampb) {
    int mode = modeBase + (int)blockIdx.z;
    const __half *Ag, *Bg; int Ktot;
    if (mode == 0)      { Ag = g_Ac16; Bg = g_Wc16; Ktot = 3*Cdim; }
    else if (mode == 1) { Ag = g_sA16; Bg = g_Ww16; Ktot = NWv*Cdim; }
    else                { Ag = g_Aa16; Bg = g_Wa16; Ktot = Cdim; }
    const int NKB = Ktot / 32;
    const int AK  = (mode == 1) ? Cdim : Ktot;

    extern __shared__ char smem[];
    uint32_t sbase = smem_u32(smem);
    int tid = threadIdx.x, lane = tid & 31, wid = tid >> 5;
    int wm = wid >> 2, wn = wid & 3;
    int m0 = blockIdx.y * 128, n0 = blockIdx.x * 64;

    // A loader: r 0..127, hf 0/1 (16-elem half)
    int r = tid >> 1, hf_ = tid & 1;
    const __half* gA = Ag + (size_t)(m0 + r)*AK + hf_*16;
    uint32_t sAd = sbase + (uint32_t)(r*SPADH + hf_*16)*2;
    // B loader: rb 0..63, q 0..3 (8-elem quarter)
    int rb = tid >> 2, q = tid & 3;
    const __half* gB = Bg + (size_t)(n0 + rb)*Ktot + q*8;
    uint32_t sBd = sbase + TO_B + (uint32_t)(rb*SPADH + q*8)*2;

    auto issue = [&](int kb) {
        uint32_t so = (uint32_t)(kb & (NSTAGE-1))*STG_BYTES;
        int ak = (mode == 1) ? (kb & 15)*32 : kb*32;
        const __half* pa = gA + ak;
        cp16(sAd + so, pa); cp16(sAd + so + 16, pa + 8);
        cp16(sBd + so, gB + (size_t)kb*32);
    };

    float acc[4][2][4];
    #pragma unroll
    for (int i = 0; i < 4; ++i)
        #pragma unroll
        for (int j = 0; j < 2; ++j)
            #pragma unroll
            for (int qq = 0; qq < 4; ++qq) acc[i][j][qq] = 0.f;

    uint32_t ph1[4], ph2[4];
    const int bIdx = m0 >> 10;
    const int tbase = m0 & (Tdim-1);

    const uint32_t aRowSel = lane & 15;
    const uint32_t aColSel = ((lane >> 4) & 1)*8;
    const uint32_t bRowSel = ((lane >> 4) & 1)*8 + (lane & 7);
    const uint32_t bColSel = ((lane >> 3) & 1)*8;

    const int NP = (NSTAGE-1 < NKB) ? NSTAGE-1 : NKB;
    for (int s = 0; s < NP; ++s) { issue(s); cp_commit(); }

    for (int kb = 0; kb < NKB; ++kb) {
        if (mode == 1 && (kb & 15) == 0) {
            int w = kb >> 4;
            float da = g_wp[bIdx*8 + w*2], dbv = g_wp[bIdx*8 + w*2 + 1];
            #pragma unroll
            for (int mt = 0; mt < 4; ++mt) {
                float t1 = (float)(tbase + wm*64 + mt*16 + (int)(lane >> 2));
                float z = (t1 - dbv)/da, z2 = z*z;
                float p1 = (1.f - z2)*expf(-0.5f*z2);
                float t2 = t1 + 8.f;
                z = (t2 - dbv)/da; z2 = z*z;
                float p2 = (1.f - z2)*expf(-0.5f*z2);
                __half2 h1v = __half2half2(__float2half_rn(p1));
                __half2 h2v = __half2half2(__float2half_rn(p2));
                ph1[mt] = *reinterpret_cast<uint32_t*>(&h1v);
                ph2[mt] = *reinterpret_cast<uint32_t*>(&h2v);
            }
        }
        cp_wait<NSTAGE-2>();
        __syncthreads();

        uint32_t sb = sbase + (uint32_t)(kb & (NSTAGE-1))*STG_BYTES;
        #pragma unroll
        for (int kk = 0; kk < 2; ++kk) {
            uint32_t kO = kk*16;
            uint32_t aF[4][4], bF[2][2];
            #pragma unroll
            for (int mt = 0; mt < 4; ++mt) {
                uint32_t row = wm*64 + mt*16 + aRowSel;
                ldmx4(sb + (row*SPADH + kO + aColSel)*2, aF[mt]);
            }
            if (mode == 1) {
                #pragma unroll
                for (int mt = 0; mt < 4; ++mt) {
                    aF[mt][0] = hmul2u(aF[mt][0], ph1[mt]);
                    aF[mt][2] = hmul2u(aF[mt][2], ph1[mt]);
                    aF[mt][1] = hmul2u(aF[mt][1], ph2[mt]);
                    aF[mt][3] = hmul2u(aF[mt][3], ph2[mt]);
                }
            }
            {
                uint32_t row = wn*16 + bRowSel;
                uint32_t r4[4];
                ldmx4(sb + TO_B + (row*SPADH + kO + bColSel)*2, r4);
                bF[0][0] = r4[0]; bF[0][1] = r4[1];
                bF[1][0] = r4[2]; bF[1][1] = r4[3];
            }
            #pragma unroll
            for (int mt = 0; mt < 4; ++mt)
                #pragma unroll
                for (int nt = 0; nt < 2; ++nt)
                    mma16816(acc[mt][nt], aF[mt], bF[nt]);
        }
        if (kb + NSTAGE-1 < NKB) issue(kb + NSTAGE-1);
        cp_commit();
    }

    // ---- epilogue ----
    const int cRow = lane >> 2, cCol2 = (lane & 3)*2;
    #pragma unroll
    for (int mt = 0; mt < 4; ++mt) {
        #pragma unroll
        for (int nt = 0; nt < 2; ++nt) {
            int col = n0 + wn*16 + nt*8 + cCol2;
            float v0 = acc[mt][nt][0], v1 = acc[mt][nt][1];
            float v2 = acc[mt][nt][2], v3 = acc[mt][nt][3];
            int row = m0 + wm*64 + mt*16 + cRow;
            if (mode == 0) {
                float b0 = g_bias0[col], b1 = g_bias0[col+1];
                v0 += b0; v1 += b1; v2 += b0; v3 += b1;
                *reinterpret_cast<__half2*>(&g_Aa16[(size_t)row*Cdim + col]) =
                    __floats2half2_rn(v0, v1);
                *reinterpret_cast<__half2*>(&g_Aa16[(size_t)(row+8)*Cdim + col]) =
                    __floats2half2_rn(v2, v3);
            } else if (mode == 1) {
                *reinterpret_cast<__half2*>(&g_s16[(size_t)row*Cdim + col]) =
                    __floats2half2_rn(v0, v1);
                *reinterpret_cast<__half2*>(&g_s16[(size_t)(row+8)*Cdim + col]) =
                    __floats2half2_rn(v2, v3);
            } else {
                float b0 = ampb[col], b1 = ampb[col+1];
                v0 = 2.f/(1.f+expf(-(v0+b0))); v1 = 2.f/(1.f+expf(-(v1+b1)));
                v2 = 2.f/(1.f+expf(-(v2+b0))); v3 = 2.f/(1.f+expf(-(v3+b1)));
                *reinterpret_cast<__half2*>(&g_a16[(size_t)row*Cdim + col]) =
                    __floats2half2_rn(v0, v1);
                *reinterpret_cast<__half2*>(&g_a16[(size_t)(row+8)*Cdim + col]) =
                    __floats2half2_rn(v2, v3);
            }
        }
    }
}

// ===================== K5: gate + residual + LayerNorm ======================
__global__ void epilogue_kernel(const float* __restrict__ x,
                                const float* __restrict__ gamma,
                                const float* __restrict__ beta,
                                float* __restrict__ out) {
    int m = blockIdx.x;
    int i = threadIdx.x;            // 128 threads
    size_t bse = (size_t)m*Cdim + i*4;
    float4 xv = *reinterpret_cast<const float4*>(&x[bse]);
    uint2 tu = *reinterpret_cast<const uint2*>(&g_Aa16[bse]);
    uint2 su = *reinterpret_cast<const uint2*>(&g_s16[bse]);
    uint2 au = *reinterpret_cast<const uint2*>(&g_a16[bse]);
    float2 t0 = __half22float2(*reinterpret_cast<__half2*>(&tu.x));
    float2 t1 = __half22float2(*reinterpret_cast<__half2*>(&tu.y));
    float2 s0 = __half22float2(*reinterpret_cast<__half2*>(&su.x));
    float2 s1 = __half22float2(*reinterpret_cast<__half2*>(&su.y));
    float2 a0 = __half22float2(*reinterpret_cast<__half2*>(&au.x));
    float2 a1 = __half22float2(*reinterpret_cast<__half2*>(&au.y));
    float4 y;
    y.x = fmaf(s0.x, a0.x, t0.x) + xv.x;
    y.y = fmaf(s0.y, a0.y, t0.y) + xv.y;
    y.z = fmaf(s1.x, a1.x, t1.x) + xv.z;
    y.w = fmaf(s1.y, a1.y, t1.y) + xv.w;

    float s  = y.x + y.y + y.z + y.w;
    float sq = y.x*y.x + y.y*y.y + y.z*y.z + y.w*y.w;
    #pragma unroll
    for (int o = 16; o; o >>= 1) {
        s  += __shfl_down_sync(0xffffffffu, s,  o);
        sq += __shfl_down_sync(0xffffffffu, sq, o);
    }
    __shared__ float rs[4], rq[4];
    int warp = i >> 5, lane = i & 31;
    if (lane == 0) { rs[warp] = s; rq[warp] = sq; }
    __syncthreads();
    float ts = rs[0]+rs[1]+rs[2]+rs[3];
    float tq = rq[0]+rq[1]+rq[2]+rq[3];
    float mu  = ts * (1.0f/Cdim);
    float var = tq * (1.0f/Cdim) - mu*mu;
    float r = rsqrtf(var + 1e-5f);

    float4 g = *reinterpret_cast<const float4*>(&gamma[i*4]);
    float4 bb= *reinterpret_cast<const float4*>(&beta[i*4]);
    float4 o4;
    o4.x = (y.x-mu)*r*g.x + bb.x;
    o4.y = (y.y-mu)*r*g.y + bb.y;
    o4.z = (y.z-mu)*r*g.z + bb.z;
    o4.w = (y.w-mu)*r*g.w + bb.w;
    *reinterpret_cast<float4*>(&out[bse]) = o4;
}

// ===================== launch ===============================================
extern "C" void kernel_launch(void* const* d_in, const int* in_sizes, int n_in,
                              void* d_out, int out_size) {
    const float* x     = (const float*)d_in[0];
    const float* tw    = (const float*)d_in[1];
    const float* tb    = (const float*)d_in[2];
    const float* sw    = (const float*)d_in[3];
    const float* sb    = (const float*)d_in[4];
    const float* slw   = (const float*)d_in[5];
    const float* slb   = (const float*)d_in[6];
    const float* cheby = (const float*)d_in[7];
    const float* hw1   = (const float*)d_in[8];
    const float* hb1   = (const float*)d_in[9];
    const float* hw2   = (const float*)d_in[10];
    const float* hb2   = (const float*)d_in[11];
    const float* amp_w = (const float*)d_in[12];
    const float* amp_b = (const float*)d_in[13];
    const float* wav_w = (const float*)d_in[14];
    const float* gamma = (const float*)d_in[15];
    const float* beta  = (const float*)d_in[16];
    float* out = (float*)d_out;

    cudaFuncSetAttribute(gemm_kernel, cudaFuncAttributeMaxDynamicSharedMemorySize, SMEM_GEMM);

    prep_all<<<2049, 256>>>(cheby, wav_w, amp_w);
    decomp_kernel<<<(SEG*Bdim*Cdim/2)/256, 256>>>(x, tw, tb, sw, sb);
    hyper_pool<<<Bdim, 512>>>(slw, slb);
    hyper_mm<<<dim3(4, Bdim, 8), 256>>>(hw1);
    hyper_psi<<<Bdim, 256>>>(hw2, hb2, hb1);
    gemm_kernel<<<dim3(8, Mrows/128, 2), 256, SMEM_GEMM>>>(0, nullptr);
    gemm_kernel<<<dim3(8, Mrows/128, 1), 256, SMEM_GEMM>>>(2, amp_b);
    epilogue_kernel<<<Mrows, 128>>>(x, gamma, beta, out);
}

// round 13
// speedup vs baseline: 1.1824x; 1.1824x over previous
#include <cuda_runtime.h>
#include <cuda_fp16.h>
#include <cstdint>
#include <math.h>

#define Bdim 16
#define Tdim 1024
#define Cdim 512
#define Kma  25
#define NWv  4
#define Mrows (Bdim*Tdim)   // 16384
#define SEG  16
#define SEGLEN (Tdim/SEG)   // 64

// ===================== scratch ==============================================
__device__ __half g_Ac16[Mrows*3*Cdim];   // cheby basis A, [m][k=(d-1)*512+c]
__device__ __half g_sA16[Mrows*Cdim];     // spike_ctx fp16 (wavelet A base)
__device__ __half g_Aa16[Mrows*Cdim];     // tout fp16 (amp A + epilogue trend)
__device__ __half g_s16 [Mrows*Cdim];     // spike_out fp16
__device__ __half g_a16 [Mrows*Cdim];     // amp_scale fp16
__device__ float  g_bias0[Cdim];
__device__ float  g_Spart[SEG][Bdim*Cdim];
__device__ float  g_tr0[Bdim*Cdim];
__device__ float  g_trN[Bdim*Cdim];
__device__ float  g_h  [Bdim*2*Cdim];
__device__ float  g_hacc[Bdim*Cdim];      // pre-activation h1 accumulator
__device__ float  g_wp [Bdim*2*NWv];      // [b][w*2 + {0:da,1:db}]
// weights transposed to [o][k], fp16
__device__ __half g_Wc16[Cdim*3*Cdim];
__device__ __half g_Ww16[Cdim*NWv*Cdim];
__device__ __half g_Wa16[Cdim*Cdim];

// ===================== helpers ==============================================
__device__ __forceinline__ uint32_t smem_u32(const void* p) {
    uint32_t a;
    asm("{ .reg .u64 t; cvta.to.shared.u64 t, %1; cvt.u32.u64 %0, t; }" : "=r"(a) : "l"(p));
    return a;
}
__device__ __forceinline__ void cp16(uint32_t dst, const void* src) {
    asm volatile("cp.async.cg.shared.global [%0], [%1], 16;" :: "r"(dst), "l"(src));
}
__device__ __forceinline__ void cp_commit() { asm volatile("cp.async.commit_group;"); }
template<int N> __device__ __forceinline__ void cp_wait() {
    asm volatile("cp.async.wait_group %0;" :: "n"(N));
}
__device__ __forceinline__ void ldmx4(uint32_t addr, uint32_t* r) {
    asm volatile("ldmatrix.sync.aligned.m8n8.x4.shared.b16 {%0,%1,%2,%3}, [%4];"
        : "=r"(r[0]), "=r"(r[1]), "=r"(r[2]), "=r"(r[3]) : "r"(addr));
}
__device__ __forceinline__ void mma16816(float* c, const uint32_t* a, const uint32_t* b) {
    asm volatile("mma.sync.aligned.m16n8k16.row.col.f32.f16.f16.f32 "
        "{%0,%1,%2,%3}, {%4,%5,%6,%7}, {%8,%9}, {%0,%1,%2,%3};"
        : "+f"(c[0]), "+f"(c[1]), "+f"(c[2]), "+f"(c[3])
        : "r"(a[0]), "r"(a[1]), "r"(a[2]), "r"(a[3]), "r"(b[0]), "r"(b[1]));
}
__device__ __forceinline__ uint32_t hmul2u(uint32_t a, uint32_t b) {
    __half2 r = __hmul2(*reinterpret_cast<__half2*>(&a), *reinterpret_cast<__half2*>(&b));
    return *reinterpret_cast<uint32_t*>(&r);
}

// ===================== K0: fused weight prep ================================
__global__ void prep_all(const float* __restrict__ cheby,
                         const float* __restrict__ wav_w,
                         const float* __restrict__ amp_w) {
    int bx = blockIdx.x;
    int tx = threadIdx.x & 31, ty = threadIdx.x >> 5;   // 32 x 8

    if (bx == 2048) {
        for (int o = threadIdx.x; o < Cdim; o += 256) {
            float s = 0.f;
            for (int c = 0; c < Cdim; ++c) s += cheby[(c*Cdim + o)*4];
            g_bias0[o] = s;
        }
        return;
    }

    const float* src; __half* dst; int Ktot, kb, ob, mode;
    if (bx < 768)       { mode = 0; src = cheby; dst = g_Wc16; Ktot = 3*Cdim;
                          kb = (bx % 48)*32;  ob = (bx / 48)*32; }
    else if (bx < 1792) { mode = 1; src = wav_w; dst = g_Ww16; Ktot = NWv*Cdim;
                          int i = bx - 768;  kb = (i % 64)*32; ob = (i / 64)*32; }
    else                { mode = 2; src = amp_w; dst = g_Wa16; Ktot = Cdim;
                          int i = bx - 1792; kb = (i % 16)*32; ob = (i / 16)*32; }

    __shared__ float tile[32][33];
    #pragma unroll
    for (int s = 0; s < 32; s += 8) {
        int k = kb + ty + s, o = ob + tx;
        float v;
        if (mode == 0) { int d = k >> 9, c = k & 511; v = src[(c*Cdim + o)*4 + d + 1]; }
        else           { v = src[(size_t)k*Cdim + o]; }
        tile[ty+s][tx] = v;
    }
    __syncthreads();
    #pragma unroll
    for (int s = 0; s < 32; s += 8) {
        int o = ob + ty + s, k = kb + tx;
        dst[(size_t)o*Ktot + k] = __float2half_rn(tile[tx][ty+s]);
    }
}

// ===================== K1: fused decomposition (scalar, SEG=16) =============
__global__ void decomp_kernel(const float* __restrict__ x,
                              const float* __restrict__ tw, const float* __restrict__ tb,
                              const float* __restrict__ sw, const float* __restrict__ sb) {
    int idx = blockIdx.x*blockDim.x + threadIdx.x;      // 131072 threads
    int c   = idx & (Cdim-1);
    int tmp = idx >> 9;
    int b   = tmp & (Bdim-1);
    int seg = tmp >> 4;
    const float* xb = x + (size_t)b*Tdim*Cdim + c;
    const float inv = 1.0f/(float)Kma;
    float w0t=tw[c*3+0], w1t=tw[c*3+1], w2t=tw[c*3+2], btc=tb[c];
    float w0s=sw[c*3+0], w1s=sw[c*3+1], w2s=sw[c*3+2], bsc=sb[c];

    int t0 = seg*SEGLEN, t1 = t0 + SEGLEN;
    float ws = 0.f;
    int tref = (seg==0) ? 0 : (t0-1);
    #pragma unroll 5
    for (int j = tref-(Kma-1); j <= tref; ++j) ws += xb[max(j,0)*Cdim];

    float tr_m1, tr_c, x_m1, x_c;
    if (seg == 0) {
        tr_c = ws*inv; tr_m1 = tr_c;
        x_c  = xb[0];  x_m1  = x_c;
    } else {
        tr_m1 = ws*inv;
        x_m1  = xb[(t0-1)*Cdim];
        ws   += xb[t0*Cdim] - xb[max(t0-Kma,0)*Cdim];
        tr_c  = ws*inv;
        x_c   = xb[t0*Cdim];
    }

    float Ssum = 0.f;
    #pragma unroll 4
    for (int t = t0; t < t1; ++t) {
        Ssum += tr_c;
        float tr_p, x_p;
        if (t+1 < Tdim) {
            x_p = xb[(t+1)*Cdim];
            ws += x_p - xb[max(t+1-Kma,0)*Cdim];
            tr_p = ws*inv;
        } else { x_p = x_c; tr_p = tr_c; }

        int m = b*Tdim + t;
        float tctx = fmaf(tr_m1,w0t, fmaf(tr_c,w1t, fmaf(tr_p,w2t, btc)));
        float xt = tanhf(tctx);
        float d2 = fmaf(2.f*xt, xt, -1.f);
        float d3 = xt * fmaf(4.f*xt, xt, -3.f);
        size_t arow = (size_t)m*(3*Cdim) + c;
        g_Ac16[arow]          = __float2half_rn(xt);
        g_Ac16[arow + Cdim]   = __float2half_rn(d2);
        g_Ac16[arow + 2*Cdim] = __float2half_rn(d3);

        float sm1 = x_m1-tr_m1, sc = x_c-tr_c, spp = x_p-tr_p;
        float sctx = fmaf(sm1,w0s, fmaf(sc,w1s, fmaf(spp,w2s, bsc)));
        g_sA16[(size_t)m*Cdim + c] = __float2half_rn(sctx);

        if (t == 0)      g_tr0[b*Cdim+c] = tr_c;
        if (t == Tdim-1) g_trN[b*Cdim+c] = tr_c;
        tr_m1 = tr_c; tr_c = tr_p; x_m1 = x_c; x_c = x_p;
    }
    g_Spart[seg][b*Cdim+c] = Ssum;
}

// ===================== K2: hypernetwork (3 kernels, R6 structure) ===========
__global__ void hyper_pool(const float* __restrict__ slw, const float* __restrict__ slb) {
    int b = blockIdx.x, c = threadIdx.x;   // 16 x 512
    g_hacc[b*Cdim + c] = 0.f;              // zero the split-K accumulator
    float S = 0.f;
    #pragma unroll
    for (int s = 0; s < SEG; ++s) S += g_Spart[s][b*Cdim+c];
    float tr0 = g_tr0[b*Cdim+c], trN = g_trN[b*Cdim+c];
    float a0 = slw[c*3+0], a1 = slw[c*3+1], a2 = slw[c*3+2];
    float sp = (a0*(S + tr0 - trN) + a1*S + a2*(S - tr0 + trN)) * (1.0f/Tdim) + slb[c];
    g_h[b*2*Cdim + c]        = sp;
    g_h[b*2*Cdim + Cdim + c] = S * (1.0f/Tdim);
}

// split-K: grid (4, 16, 8) x 256; block (cx,b,ks) does k in [ks*128, ks*128+128)
__global__ void hyper_mm(const float* __restrict__ w1) {
    int b = blockIdx.y, ks = blockIdx.z;
    int col = blockIdx.x*128 + (threadIdx.x & 127);
    int kh  = threadIdx.x >> 7;          // 0/1 -> 64-k half
    __shared__ float hs[128];
    if (threadIdx.x < 128) hs[threadIdx.x] = g_h[b*2*Cdim + ks*128 + threadIdx.x];
    __syncthreads();
    const float* wp = w1 + (size_t)(ks*128 + kh*64)*Cdim + col;
    const float* hp = hs + kh*64;
    float a0=0.f, a1=0.f, a2=0.f, a3=0.f;
    #pragma unroll 4
    for (int i = 0; i < 64; i += 4) {
        a0 = fmaf(hp[i+0], wp[(i+0)*Cdim], a0);
        a1 = fmaf(hp[i+1], wp[(i+1)*Cdim], a1);
        a2 = fmaf(hp[i+2], wp[(i+2)*Cdim], a2);
        a3 = fmaf(hp[i+3], wp[(i+3)*Cdim], a3);
    }
    atomicAdd(&g_hacc[b*Cdim + col], (a0+a1)+(a2+a3));
}

__global__ void hyper_psi(const float* __restrict__ w2, const float* __restrict__ b2,
                          const float* __restrict__ b1) {
    int b = blockIdx.x;
    int j = threadIdx.x;                      // 256
    int warp = j >> 5, lane = j & 31;
    __shared__ float params_s[2*NWv];
    if (warp < 2*NWv) {
        float v = 0.f;
        for (int jj = lane; jj < Cdim; jj += 32) {
            float hv = g_hacc[b*Cdim + jj] + b1[jj];
            hv = hv / (1.f + expf(-hv));      // silu
            v = fmaf(hv, w2[jj*(2*NWv) + warp], v);
        }
        #pragma unroll
        for (int o = 16; o; o >>= 1) v += __shfl_down_sync(0xffffffffu, v, o);
        if (lane == 0) params_s[warp] = v + b2[warp];
    }
    __syncthreads();
    if (j < NWv) {
        float a = params_s[j*2+0], bb = params_s[j*2+1];
        g_wp[b*2*NWv + j*2 + 0] = ((a > 20.f) ? a : log1pf(expf(a))) + 0.01f;
        g_wp[b*2*NWv + j*2 + 1] = (float)Tdim / (1.f + expf(-bb));
    }
}

// ===================== fp16 mma GEMM (K32, 4 stages, 2 CTA/SM) ==============
// mode 0: tout16 = Acheby @ Wc + bias0 -> g_Aa16
// mode 1: sout   = (psi (x) sctx) @ Ww -> g_s16 (psi applied to A fragments)
// mode 2: amp    = 2*sigmoid(tout16 @ Wa + amp_b) -> g_a16
#define SPADH 40
#define TO_B  (128*SPADH*2)            // 10240 B
#define STG_BYTES (2*128*SPADH*2)      // 20480 B
#define NSTAGE 4
#define SMEM_GEMM (NSTAGE*STG_BYTES)   // 81920 B  (2 CTAs = 160KB)

__global__ __launch_bounds__(256, 2)
void gemm_kernel(int modeBase, const float* __restrict__ ampb) {
    int mode = modeBase + (int)blockIdx.z;
    const __half *Ag, *Bg; int Ktot;
    if (mode == 0)      { Ag = g_Ac16; Bg = g_Wc16; Ktot = 3*Cdim; }
    else if (mode == 1) { Ag = g_sA16; Bg = g_Ww16; Ktot = NWv*Cdim; }
    else                { Ag = g_Aa16; Bg = g_Wa16; Ktot = Cdim; }
    const int NKB = Ktot / 32;
    const int AK  = (mode == 1) ? Cdim : Ktot;   // A row length (wavelet wraps)

    extern __shared__ char smem[];
    uint32_t sbase = smem_u32(smem);
    int tid = threadIdx.x, lane = tid & 31, wid = tid >> 5;
    int wm = wid >> 2, wn = wid & 3;
    int m0 = blockIdx.y * 128, n0 = blockIdx.x * 128;

    int r = tid >> 1, hf_ = tid & 1;
    const __half* gA = Ag + (size_t)(m0 + r)*AK + hf_*16;
    const __half* gB = Bg + (size_t)(n0 + r)*Ktot + hf_*16;
    uint32_t sAd = sbase + (uint32_t)(r*SPADH + hf_*16)*2;
    uint32_t sBd = sAd + TO_B;

    auto issue = [&](int kb) {
        uint32_t so = (uint32_t)(kb & (NSTAGE-1))*STG_BYTES;
        int ak = (mode == 1) ? (kb & 15)*32 : kb*32;
        const __half* pa = gA + ak;
        const __half* pb = gB + (size_t)kb*32;
        cp16(sAd + so, pa); cp16(sAd + so + 16, pa + 8);
        cp16(sBd + so, pb); cp16(sBd + so + 16, pb + 8);
    };

    float acc[4][4][4];
    #pragma unroll
    for (int i = 0; i < 4; ++i)
        #pragma unroll
        for (int j = 0; j < 4; ++j)
            #pragma unroll
            for (int q = 0; q < 4; ++q) acc[i][j][q] = 0.f;

    uint32_t ph1[4], ph2[4];
    const int bIdx = m0 >> 10;
    const int tbase = m0 & (Tdim-1);

    const uint32_t aRowSel = lane & 15;
    const uint32_t aColSel = ((lane >> 4) & 1)*8;
    const uint32_t bRowSel = ((lane >> 4) & 1)*8 + (lane & 7);
    const uint32_t bColSel = ((lane >> 3) & 1)*8;

    const int NP = (NSTAGE-1 < NKB) ? NSTAGE-1 : NKB;
    for (int s = 0; s < NP; ++s) { issue(s); cp_commit(); }

    for (int kb = 0; kb < NKB; ++kb) {
        if (mode == 1 && (kb & 15) == 0) {
            int w = kb >> 4;
            float da = g_wp[bIdx*8 + w*2], dbv = g_wp[bIdx*8 + w*2 + 1];
            #pragma unroll
            for (int mt = 0; mt < 4; ++mt) {
                float t1 = (float)(tbase + wm*64 + mt*16 + (int)(lane >> 2));
                float z = (t1 - dbv)/da, z2 = z*z;
                float p1 = (1.f - z2)*expf(-0.5f*z2);
                float t2 = t1 + 8.f;
                z = (t2 - dbv)/da; z2 = z*z;
                float p2 = (1.f - z2)*expf(-0.5f*z2);
                __half2 h1v = __half2half2(__float2half_rn(p1));
                __half2 h2v = __half2half2(__float2half_rn(p2));
                ph1[mt] = *reinterpret_cast<uint32_t*>(&h1v);
                ph2[mt] = *reinterpret_cast<uint32_t*>(&h2v);
            }
        }
        cp_wait<NSTAGE-2>();
        __syncthreads();

        uint32_t sb = sbase + (uint32_t)(kb & (NSTAGE-1))*STG_BYTES;
        #pragma unroll
        for (int kk = 0; kk < 2; ++kk) {
            uint32_t kO = kk*16;
            uint32_t aF[4][4], bF[4][2];
            #pragma unroll
            for (int mt = 0; mt < 4; ++mt) {
                uint32_t row = wm*64 + mt*16 + aRowSel;
                ldmx4(sb + (row*SPADH + kO + aColSel)*2, aF[mt]);
            }
            if (mode == 1) {
                #pragma unroll
                for (int mt = 0; mt < 4; ++mt) {
                    aF[mt][0] = hmul2u(aF[mt][0], ph1[mt]);
                    aF[mt][2] = hmul2u(aF[mt][2], ph1[mt]);
                    aF[mt][1] = hmul2u(aF[mt][1], ph2[mt]);
                    aF[mt][3] = hmul2u(aF[mt][3], ph2[mt]);
                }
            }
            #pragma unroll
            for (int p = 0; p < 2; ++p) {
                uint32_t row = wn*32 + p*16 + bRowSel;
                uint32_t r4[4];
                ldmx4(sb + TO_B + (row*SPADH + kO + bColSel)*2, r4);
                bF[p*2+0][0] = r4[0]; bF[p*2+0][1] = r4[1];
                bF[p*2+1][0] = r4[2]; bF[p*2+1][1] = r4[3];
            }
            #pragma unroll
            for (int mt = 0; mt < 4; ++mt)
                #pragma unroll
                for (int nt = 0; nt < 4; ++nt)
                    mma16816(acc[mt][nt], aF[mt], bF[nt]);
        }
        if (kb + NSTAGE-1 < NKB) issue(kb + NSTAGE-1);
        cp_commit();
    }

    // ---- epilogue ----
    const int cRow = lane >> 2, cCol2 = (lane & 3)*2;
    #pragma unroll
    for (int mt = 0; mt < 4; ++mt) {
        #pragma unroll
        for (int nt = 0; nt < 4; ++nt) {
            int col = n0 + wn*32 + nt*8 + cCol2;
            float v0 = acc[mt][nt][0], v1 = acc[mt][nt][1];
            float v2 = acc[mt][nt][2], v3 = acc[mt][nt][3];
            int row = m0 + wm*64 + mt*16 + cRow;
            if (mode == 0) {
                float b0 = g_bias0[col], b1 = g_bias0[col+1];
                v0 += b0; v1 += b1; v2 += b0; v3 += b1;
                *reinterpret_cast<__half2*>(&g_Aa16[(size_t)row*Cdim + col]) =
                    __floats2half2_rn(v0, v1);
                *reinterpret_cast<__half2*>(&g_Aa16[(size_t)(row+8)*Cdim + col]) =
                    __floats2half2_rn(v2, v3);
            } else if (mode == 1) {
                *reinterpret_cast<__half2*>(&g_s16[(size_t)row*Cdim + col]) =
                    __floats2half2_rn(v0, v1);
                *reinterpret_cast<__half2*>(&g_s16[(size_t)(row+8)*Cdim + col]) =
                    __floats2half2_rn(v2, v3);
            } else {
                float b0 = ampb[col], b1 = ampb[col+1];
                v0 = 2.f/(1.f+expf(-(v0+b0))); v1 = 2.f/(1.f+expf(-(v1+b1)));
                v2 = 2.f/(1.f+expf(-(v2+b0))); v3 = 2.f/(1.f+expf(-(v3+b1)));
                *reinterpret_cast<__half2*>(&g_a16[(size_t)row*Cdim + col]) =
                    __floats2half2_rn(v0, v1);
                *reinterpret_cast<__half2*>(&g_a16[(size_t)(row+8)*Cdim + col]) =
                    __floats2half2_rn(v2, v3);
            }
        }
    }
}

// ===================== K5: gate + residual + LayerNorm ======================
__global__ void epilogue_kernel(const float* __restrict__ x,
                                const float* __restrict__ gamma,
                                const float* __restrict__ beta,
                                float* __restrict__ out) {
    int m = blockIdx.x;
    int i = threadIdx.x;            // 128 threads, 4 elems each
    size_t bse = (size_t)m*Cdim + i*4;
    float4 xv = *reinterpret_cast<const float4*>(&x[bse]);
    uint2 tu = *reinterpret_cast<const uint2*>(&g_Aa16[bse]);
    uint2 su = *reinterpret_cast<const uint2*>(&g_s16[bse]);
    uint2 au = *reinterpret_cast<const uint2*>(&g_a16[bse]);
    float2 t0 = __half22float2(*reinterpret_cast<__half2*>(&tu.x));
    float2 t1 = __half22float2(*reinterpret_cast<__half2*>(&tu.y));
    float2 s0 = __half22float2(*reinterpret_cast<__half2*>(&su.x));
    float2 s1 = __half22float2(*reinterpret_cast<__half2*>(&su.y));
    float2 a0 = __half22float2(*reinterpret_cast<__half2*>(&au.x));
    float2 a1 = __half22float2(*reinterpret_cast<__half2*>(&au.y));
    float4 y;
    y.x = fmaf(s0.x, a0.x, t0.x) + xv.x;
    y.y = fmaf(s0.y, a0.y, t0.y) + xv.y;
    y.z = fmaf(s1.x, a1.x, t1.x) + xv.z;
    y.w = fmaf(s1.y, a1.y, t1.y) + xv.w;

    float s  = y.x + y.y + y.z + y.w;
    float sq = y.x*y.x + y.y*y.y + y.z*y.z + y.w*y.w;
    #pragma unroll
    for (int o = 16; o; o >>= 1) {
        s  += __shfl_down_sync(0xffffffffu, s,  o);
        sq += __shfl_down_sync(0xffffffffu, sq, o);
    }
    __shared__ float rs[4], rq[4];
    int warp = i >> 5, lane = i & 31;
    if (lane == 0) { rs[warp] = s; rq[warp] = sq; }
    __syncthreads();
    float ts = rs[0]+rs[1]+rs[2]+rs[3];
    float tq = rq[0]+rq[1]+rq[2]+rq[3];
    float mu  = ts * (1.0f/Cdim);
    float var = tq * (1.0f/Cdim) - mu*mu;
    float r = rsqrtf(var + 1e-5f);

    float4 g = *reinterpret_cast<const float4*>(&gamma[i*4]);
    float4 bb= *reinterpret_cast<const float4*>(&beta[i*4]);
    float4 o4;
    o4.x = (y.x-mu)*r*g.x + bb.x;
    o4.y = (y.y-mu)*r*g.y + bb.y;
    o4.z = (y.z-mu)*r*g.z + bb.z;
    o4.w = (y.w-mu)*r*g.w + bb.w;
    *reinterpret_cast<float4*>(&out[bse]) = o4;
}

// ===================== launch ===============================================
extern "C" void kernel_launch(void* const* d_in, const int* in_sizes, int n_in,
                              void* d_out, int out_size) {
    const float* x     = (const float*)d_in[0];
    const float* tw    = (const float*)d_in[1];
    const float* tb    = (const float*)d_in[2];
    const float* sw    = (const float*)d_in[3];
    const float* sb    = (const float*)d_in[4];
    const float* slw   = (const float*)d_in[5];
    const float* slb   = (const float*)d_in[6];
    const float* cheby = (const float*)d_in[7];
    const float* hw1   = (const float*)d_in[8];
    const float* hb1   = (const float*)d_in[9];
    const float* hw2   = (const float*)d_in[10];
    const float* hb2   = (const float*)d_in[11];
    const float* amp_w = (const float*)d_in[12];
    const float* amp_b = (const float*)d_in[13];
    const float* wav_w = (const float*)d_in[14];
    const float* gamma = (const float*)d_in[15];
    const float* beta  = (const float*)d_in[16];
    float* out = (float*)d_out;

    cudaFuncSetAttribute(gemm_kernel, cudaFuncAttributeMaxDynamicSharedMemorySize, SMEM_GEMM);

    prep_all<<<2049, 256>>>(cheby, wav_w, amp_w);
    decomp_kernel<<<(SEG*Bdim*Cdim)/256, 256>>>(x, tw, tb, sw, sb);   // 512 blocks
    hyper_pool<<<Bdim, 512>>>(slw, slb);
    hyper_mm<<<dim3(4, Bdim, 8), 256>>>(hw1);
    hyper_psi<<<Bdim, 256>>>(hw2, hb2, hb1);
    gemm_kernel<<<dim3(4, Mrows/128, 2), 256, SMEM_GEMM>>>(0, nullptr);
    gemm_kernel<<<dim3(4, Mrows/128, 1), 256, SMEM_GEMM>>>(2, amp_b);
    epilogue_kernel<<<Mrows, 128>>>(x, gamma, beta, out);
}

// round 14
// speedup vs baseline: 1.2014x; 1.0161x over previous
#include <cuda_runtime.h>
#include <cuda_fp16.h>
#include <cstdint>
#include <math.h>

#define Bdim 16
#define Tdim 1024
#define Cdim 512
#define Kma  25
#define NWv  4
#define Mrows (Bdim*Tdim)   // 16384
#define SEG  32
#define SEGLEN (Tdim/SEG)   // 32

// ===================== scratch ==============================================
__device__ __half g_Ac16[Mrows*3*Cdim];   // cheby basis A, [m][k=(d-1)*512+c]
__device__ __half g_sA16[Mrows*Cdim];     // spike_ctx fp16 (wavelet A base)
__device__ __half g_Aa16[Mrows*Cdim];     // tout fp16 (amp A + epilogue trend)
__device__ __half g_s16 [Mrows*Cdim];     // spike_out fp16
__device__ __half g_a16 [Mrows*Cdim];     // amp_scale fp16
__device__ float  g_bias0[Cdim];
__device__ float  g_Spart[SEG][Bdim*Cdim];
__device__ float  g_tr0[Bdim*Cdim];
__device__ float  g_trN[Bdim*Cdim];
__device__ float  g_h  [Bdim*2*Cdim];
__device__ float  g_hacc[Bdim*Cdim];      // pre-activation h1 accumulator
__device__ float  g_wp [Bdim*2*NWv];      // [b][w*2 + {0:da,1:db}]
// weights transposed to [o][k], fp16
__device__ __half g_Wc16[Cdim*3*Cdim];
__device__ __half g_Ww16[Cdim*NWv*Cdim];
__device__ __half g_Wa16[Cdim*Cdim];

// ===================== helpers ==============================================
__device__ __forceinline__ uint32_t smem_u32(const void* p) {
    uint32_t a;
    asm("{ .reg .u64 t; cvta.to.shared.u64 t, %1; cvt.u32.u64 %0, t; }" : "=r"(a) : "l"(p));
    return a;
}
__device__ __forceinline__ void cp16(uint32_t dst, const void* src) {
    asm volatile("cp.async.cg.shared.global [%0], [%1], 16;" :: "r"(dst), "l"(src));
}
__device__ __forceinline__ void cp_commit() { asm volatile("cp.async.commit_group;"); }
template<int N> __device__ __forceinline__ void cp_wait() {
    asm volatile("cp.async.wait_group %0;" :: "n"(N));
}
__device__ __forceinline__ void ldmx4(uint32_t addr, uint32_t* r) {
    asm volatile("ldmatrix.sync.aligned.m8n8.x4.shared.b16 {%0,%1,%2,%3}, [%4];"
        : "=r"(r[0]), "=r"(r[1]), "=r"(r[2]), "=r"(r[3]) : "r"(addr));
}
__device__ __forceinline__ void mma16816(float* c, const uint32_t* a, const uint32_t* b) {
    asm volatile("mma.sync.aligned.m16n8k16.row.col.f32.f16.f16.f32 "
        "{%0,%1,%2,%3}, {%4,%5,%6,%7}, {%8,%9}, {%0,%1,%2,%3};"
        : "+f"(c[0]), "+f"(c[1]), "+f"(c[2]), "+f"(c[3])
        : "r"(a[0]), "r"(a[1]), "r"(a[2]), "r"(a[3]), "r"(b[0]), "r"(b[1]));
}
__device__ __forceinline__ uint32_t hmul2u(uint32_t a, uint32_t b) {
    __half2 r = __hmul2(*reinterpret_cast<__half2*>(&a), *reinterpret_cast<__half2*>(&b));
    return *reinterpret_cast<uint32_t*>(&r);
}

// ===================== K0: fused weight prep ================================
__global__ void prep_all(const float* __restrict__ cheby,
                         const float* __restrict__ wav_w,
                         const float* __restrict__ amp_w) {
    int bx = blockIdx.x;
    int tx = threadIdx.x & 31, ty = threadIdx.x >> 5;   // 32 x 8

    if (bx == 2048) {
        for (int o = threadIdx.x; o < Cdim; o += 256) {
            float s = 0.f;
            for (int c = 0; c < Cdim; ++c) s += cheby[(c*Cdim + o)*4];
            g_bias0[o] = s;
        }
        return;
    }

    const float* src; __half* dst; int Ktot, kb, ob, mode;
    if (bx < 768)       { mode = 0; src = cheby; dst = g_Wc16; Ktot = 3*Cdim;
                          kb = (bx % 48)*32;  ob = (bx / 48)*32; }
    else if (bx < 1792) { mode = 1; src = wav_w; dst = g_Ww16; Ktot = NWv*Cdim;
                          int i = bx - 768;  kb = (i % 64)*32; ob = (i / 64)*32; }
    else                { mode = 2; src = amp_w; dst = g_Wa16; Ktot = Cdim;
                          int i = bx - 1792; kb = (i % 16)*32; ob = (i / 16)*32; }

    __shared__ float tile[32][33];
    #pragma unroll
    for (int s = 0; s < 32; s += 8) {
        int k = kb + ty + s, o = ob + tx;
        float v;
        if (mode == 0) { int d = k >> 9, c = k & 511; v = src[(c*Cdim + o)*4 + d + 1]; }
        else           { v = src[(size_t)k*Cdim + o]; }
        tile[ty+s][tx] = v;
    }
    __syncthreads();
    #pragma unroll
    for (int s = 0; s < 32; s += 8) {
        int o = ob + ty + s, k = kb + tx;
        dst[(size_t)o*Ktot + k] = __float2half_rn(tile[tx][ty+s]);
    }
}

// ===================== K1: fused decomposition (scalar, SEG=32) =============
__global__ void decomp_kernel(const float* __restrict__ x,
                              const float* __restrict__ tw, const float* __restrict__ tb,
                              const float* __restrict__ sw, const float* __restrict__ sb) {
    int idx = blockIdx.x*blockDim.x + threadIdx.x;      // 262144 threads
    int c   = idx & (Cdim-1);
    int tmp = idx >> 9;
    int b   = tmp & (Bdim-1);
    int seg = tmp >> 4;
    const float* xb = x + (size_t)b*Tdim*Cdim + c;
    const float inv = 1.0f/(float)Kma;
    float w0t=tw[c*3+0], w1t=tw[c*3+1], w2t=tw[c*3+2], btc=tb[c];
    float w0s=sw[c*3+0], w1s=sw[c*3+1], w2s=sw[c*3+2], bsc=sb[c];

    int t0 = seg*SEGLEN, t1 = t0 + SEGLEN;
    float ws = 0.f;
    int tref = (seg==0) ? 0 : (t0-1);
    #pragma unroll 5
    for (int j = tref-(Kma-1); j <= tref; ++j) ws += xb[max(j,0)*Cdim];

    float tr_m1, tr_c, x_m1, x_c;
    if (seg == 0) {
        tr_c = ws*inv; tr_m1 = tr_c;
        x_c  = xb[0];  x_m1  = x_c;
    } else {
        tr_m1 = ws*inv;
        x_m1  = xb[(t0-1)*Cdim];
        ws   += xb[t0*Cdim] - xb[max(t0-Kma,0)*Cdim];
        tr_c  = ws*inv;
        x_c   = xb[t0*Cdim];
    }

    float Ssum = 0.f;
    #pragma unroll 4
    for (int t = t0; t < t1; ++t) {
        Ssum += tr_c;
        float tr_p, x_p;
        if (t+1 < Tdim) {
            x_p = xb[(t+1)*Cdim];
            ws += x_p - xb[max(t+1-Kma,0)*Cdim];
            tr_p = ws*inv;
        } else { x_p = x_c; tr_p = tr_c; }

        int m = b*Tdim + t;
        float tctx = fmaf(tr_m1,w0t, fmaf(tr_c,w1t, fmaf(tr_p,w2t, btc)));
        float xt = tanhf(tctx);
        float d2 = fmaf(2.f*xt, xt, -1.f);
        float d3 = xt * fmaf(4.f*xt, xt, -3.f);
        size_t arow = (size_t)m*(3*Cdim) + c;
        g_Ac16[arow]          = __float2half_rn(xt);
        g_Ac16[arow + Cdim]   = __float2half_rn(d2);
        g_Ac16[arow + 2*Cdim] = __float2half_rn(d3);

        float sm1 = x_m1-tr_m1, sc = x_c-tr_c, spp = x_p-tr_p;
        float sctx = fmaf(sm1,w0s, fmaf(sc,w1s, fmaf(spp,w2s, bsc)));
        g_sA16[(size_t)m*Cdim + c] = __float2half_rn(sctx);

        if (t == 0)      g_tr0[b*Cdim+c] = tr_c;
        if (t == Tdim-1) g_trN[b*Cdim+c] = tr_c;
        tr_m1 = tr_c; tr_c = tr_p; x_m1 = x_c; x_c = x_p;
    }
    g_Spart[seg][b*Cdim+c] = Ssum;
}

// ===================== K2: hypernetwork (3 kernels) =========================
__global__ void hyper_pool(const float* __restrict__ slw, const float* __restrict__ slb) {
    int b = blockIdx.x, c = threadIdx.x;   // 16 x 512
    g_hacc[b*Cdim + c] = 0.f;              // zero the split-K accumulator
    float S = 0.f;
    #pragma unroll
    for (int s = 0; s < SEG; ++s) S += g_Spart[s][b*Cdim+c];
    float tr0 = g_tr0[b*Cdim+c], trN = g_trN[b*Cdim+c];
    float a0 = slw[c*3+0], a1 = slw[c*3+1], a2 = slw[c*3+2];
    float sp = (a0*(S + tr0 - trN) + a1*S + a2*(S - tr0 + trN)) * (1.0f/Tdim) + slb[c];
    g_h[b*2*Cdim + c]        = sp;
    g_h[b*2*Cdim + Cdim + c] = S * (1.0f/Tdim);
}

// split-K: grid (4, 16, 8) x 256; block (cx,b,ks) does k in [ks*128, ks*128+128)
__global__ void hyper_mm(const float* __restrict__ w1) {
    int b = blockIdx.y, ks = blockIdx.z;
    int col = blockIdx.x*128 + (threadIdx.x & 127);
    int kh  = threadIdx.x >> 7;          // 0/1 -> 64-k half
    __shared__ float hs[128];
    if (threadIdx.x < 128) hs[threadIdx.x] = g_h[b*2*Cdim + ks*128 + threadIdx.x];
    __syncthreads();
    const float* wp = w1 + (size_t)(ks*128 + kh*64)*Cdim + col;
    const float* hp = hs + kh*64;
    float a0=0.f, a1=0.f, a2=0.f, a3=0.f;
    #pragma unroll 4
    for (int i = 0; i < 64; i += 4) {
        a0 = fmaf(hp[i+0], wp[(i+0)*Cdim], a0);
        a1 = fmaf(hp[i+1], wp[(i+1)*Cdim], a1);
        a2 = fmaf(hp[i+2], wp[(i+2)*Cdim], a2);
        a3 = fmaf(hp[i+3], wp[(i+3)*Cdim], a3);
    }
    atomicAdd(&g_hacc[b*Cdim + col], (a0+a1)+(a2+a3));
}

__global__ void hyper_psi(const float* __restrict__ w2, const float* __restrict__ b2,
                          const float* __restrict__ b1) {
    int b = blockIdx.x;
    int j = threadIdx.x;                      // 256
    int warp = j >> 5, lane = j & 31;
    __shared__ float params_s[2*NWv];
    if (warp < 2*NWv) {
        float v = 0.f;
        for (int jj = lane; jj < Cdim; jj += 32) {
            float hv = g_hacc[b*Cdim + jj] + b1[jj];
            hv = hv / (1.f + expf(-hv));      // silu
            v = fmaf(hv, w2[jj*(2*NWv) + warp], v);
        }
        #pragma unroll
        for (int o = 16; o; o >>= 1) v += __shfl_down_sync(0xffffffffu, v, o);
        if (lane == 0) params_s[warp] = v + b2[warp];
    }
    __syncthreads();
    if (j < NWv) {
        float a = params_s[j*2+0], bb = params_s[j*2+1];
        g_wp[b*2*NWv + j*2 + 0] = ((a > 20.f) ? a : log1pf(expf(a))) + 0.01f;
        g_wp[b*2*NWv + j*2 + 1] = (float)Tdim / (1.f + expf(-bb));
    }
}

// ===================== fp16 mma GEMM (K32, 4 stages, 2 CTA/SM) ==============
// mode 0: tout16 = Acheby @ Wc + bias0 -> g_Aa16
// mode 1: sout   = (psi (x) sctx) @ Ww -> g_s16 (psi applied to A fragments)
// mode 2: amp    = 2*sigmoid(tout16 @ Wa + amp_b) -> g_a16
#define SPADH 40
#define TO_B  (128*SPADH*2)            // 10240 B
#define STG_BYTES (2*128*SPADH*2)      // 20480 B
#define NSTAGE 4
#define SMEM_GEMM (NSTAGE*STG_BYTES)   // 81920 B  (2 CTAs = 160KB)

__global__ __launch_bounds__(256, 2)
void gemm_kernel(int modeBase, const float* __restrict__ ampb) {
    int mode = modeBase + (int)blockIdx.z;
    const __half *Ag, *Bg; int Ktot;
    if (mode == 0)      { Ag = g_Ac16; Bg = g_Wc16; Ktot = 3*Cdim; }
    else if (mode == 1) { Ag = g_sA16; Bg = g_Ww16; Ktot = NWv*Cdim; }
    else                { Ag = g_Aa16; Bg = g_Wa16; Ktot = Cdim; }
    const int NKB = Ktot / 32;
    const int AK  = (mode == 1) ? Cdim : Ktot;   // A row length (wavelet wraps)

    extern __shared__ char smem[];
    uint32_t sbase = smem_u32(smem);
    int tid = threadIdx.x, lane = tid & 31, wid = tid >> 5;
    int wm = wid >> 2, wn = wid & 3;
    int m0 = blockIdx.y * 128, n0 = blockIdx.x * 128;

    int r = tid >> 1, hf_ = tid & 1;
    const __half* gA = Ag + (size_t)(m0 + r)*AK + hf_*16;
    const __half* gB = Bg + (size_t)(n0 + r)*Ktot + hf_*16;
    uint32_t sAd = sbase + (uint32_t)(r*SPADH + hf_*16)*2;
    uint32_t sBd = sAd + TO_B;

    auto issue = [&](int kb) {
        uint32_t so = (uint32_t)(kb & (NSTAGE-1))*STG_BYTES;
        int ak = (mode == 1) ? (kb & 15)*32 : kb*32;
        const __half* pa = gA + ak;
        const __half* pb = gB + (size_t)kb*32;
        cp16(sAd + so, pa); cp16(sAd + so + 16, pa + 8);
        cp16(sBd + so, pb); cp16(sBd + so + 16, pb + 8);
    };

    float acc[4][4][4];
    #pragma unroll
    for (int i = 0; i < 4; ++i)
        #pragma unroll
        for (int j = 0; j < 4; ++j)
            #pragma unroll
            for (int q = 0; q < 4; ++q) acc[i][j][q] = 0.f;

    uint32_t ph1[4], ph2[4];
    const int bIdx = m0 >> 10;
    const int tbase = m0 & (Tdim-1);

    const uint32_t aRowSel = lane & 15;
    const uint32_t aColSel = ((lane >> 4) & 1)*8;
    const uint32_t bRowSel = ((lane >> 4) & 1)*8 + (lane & 7);
    const uint32_t bColSel = ((lane >> 3) & 1)*8;

    const int NP = (NSTAGE-1 < NKB) ? NSTAGE-1 : NKB;
    for (int s = 0; s < NP; ++s) { issue(s); cp_commit(); }

    for (int kb = 0; kb < NKB; ++kb) {
        if (mode == 1 && (kb & 15) == 0) {
            int w = kb >> 4;
            float da = g_wp[bIdx*8 + w*2], dbv = g_wp[bIdx*8 + w*2 + 1];
            #pragma unroll
            for (int mt = 0; mt < 4; ++mt) {
                float t1 = (float)(tbase + wm*64 + mt*16 + (int)(lane >> 2));
                float z = (t1 - dbv)/da, z2 = z*z;
                float p1 = (1.f - z2)*expf(-0.5f*z2);
                float t2 = t1 + 8.f;
                z = (t2 - dbv)/da; z2 = z*z;
                float p2 = (1.f - z2)*expf(-0.5f*z2);
                __half2 h1v = __half2half2(__float2half_rn(p1));
                __half2 h2v = __half2half2(__float2half_rn(p2));
                ph1[mt] = *reinterpret_cast<uint32_t*>(&h1v);
                ph2[mt] = *reinterpret_cast<uint32_t*>(&h2v);
            }
        }
        cp_wait<NSTAGE-2>();
        __syncthreads();

        uint32_t sb = sbase + (uint32_t)(kb & (NSTAGE-1))*STG_BYTES;
        #pragma unroll
        for (int kk = 0; kk < 2; ++kk) {
            uint32_t kO = kk*16;
            uint32_t aF[4][4], bF[4][2];
            #pragma unroll
            for (int mt = 0; mt < 4; ++mt) {
                uint32_t row = wm*64 + mt*16 + aRowSel;
                ldmx4(sb + (row*SPADH + kO + aColSel)*2, aF[mt]);
            }
            if (mode == 1) {
                #pragma unroll
                for (int mt = 0; mt < 4; ++mt) {
                    aF[mt][0] = hmul2u(aF[mt][0], ph1[mt]);
                    aF[mt][2] = hmul2u(aF[mt][2], ph1[mt]);
                    aF[mt][1] = hmul2u(aF[mt][1], ph2[mt]);
                    aF[mt][3] = hmul2u(aF[mt][3], ph2[mt]);
                }
            }
            #pragma unroll
            for (int p = 0; p < 2; ++p) {
                uint32_t row = wn*32 + p*16 + bRowSel;
                uint32_t r4[4];
                ldmx4(sb + TO_B + (row*SPADH + kO + bColSel)*2, r4);
                bF[p*2+0][0] = r4[0]; bF[p*2+0][1] = r4[1];
                bF[p*2+1][0] = r4[2]; bF[p*2+1][1] = r4[3];
            }
            #pragma unroll
            for (int mt = 0; mt < 4; ++mt)
                #pragma unroll
                for (int nt = 0; nt < 4; ++nt)
                    mma16816(acc[mt][nt], aF[mt], bF[nt]);
        }
        if (kb + NSTAGE-1 < NKB) issue(kb + NSTAGE-1);
        cp_commit();
    }

    // ---- epilogue ----
    const int cRow = lane >> 2, cCol2 = (lane & 3)*2;
    #pragma unroll
    for (int mt = 0; mt < 4; ++mt) {
        #pragma unroll
        for (int nt = 0; nt < 4; ++nt) {
            int col = n0 + wn*32 + nt*8 + cCol2;
            float v0 = acc[mt][nt][0], v1 = acc[mt][nt][1];
            float v2 = acc[mt][nt][2], v3 = acc[mt][nt][3];
            int row = m0 + wm*64 + mt*16 + cRow;
            if (mode == 0) {
                float b0 = g_bias0[col], b1 = g_bias0[col+1];
                v0 += b0; v1 += b1; v2 += b0; v3 += b1;
                *reinterpret_cast<__half2*>(&g_Aa16[(size_t)row*Cdim + col]) =
                    __floats2half2_rn(v0, v1);
                *reinterpret_cast<__half2*>(&g_Aa16[(size_t)(row+8)*Cdim + col]) =
                    __floats2half2_rn(v2, v3);
            } else if (mode == 1) {
                *reinterpret_cast<__half2*>(&g_s16[(size_t)row*Cdim + col]) =
                    __floats2half2_rn(v0, v1);
                *reinterpret_cast<__half2*>(&g_s16[(size_t)(row+8)*Cdim + col]) =
                    __floats2half2_rn(v2, v3);
            } else {
                float b0 = ampb[col], b1 = ampb[col+1];
                v0 = 2.f/(1.f+expf(-(v0+b0))); v1 = 2.f/(1.f+expf(-(v1+b1)));
                v2 = 2.f/(1.f+expf(-(v2+b0))); v3 = 2.f/(1.f+expf(-(v3+b1)));
                *reinterpret_cast<__half2*>(&g_a16[(size_t)row*Cdim + col]) =
                    __floats2half2_rn(v0, v1);
                *reinterpret_cast<__half2*>(&g_a16[(size_t)(row+8)*Cdim + col]) =
                    __floats2half2_rn(v2, v3);
            }
        }
    }
}

// ===================== K5: gate + residual + LayerNorm (2 rows/block) =======
__global__ void epilogue_kernel(const float* __restrict__ x,
                                const float* __restrict__ gamma,
                                const float* __restrict__ beta,
                                float* __restrict__ out) {
    int half = threadIdx.x >> 7;          // 0/1 -> row within block
    int i    = threadIdx.x & 127;         // 128 threads per row
    int m    = blockIdx.x*2 + half;
    size_t bse = (size_t)m*Cdim + i*4;
    float4 xv = *reinterpret_cast<const float4*>(&x[bse]);
    uint2 tu = *reinterpret_cast<const uint2*>(&g_Aa16[bse]);
    uint2 su = *reinterpret_cast<const uint2*>(&g_s16[bse]);
    uint2 au = *reinterpret_cast<const uint2*>(&g_a16[bse]);
    float2 t0 = __half22float2(*reinterpret_cast<__half2*>(&tu.x));
    float2 t1 = __half22float2(*reinterpret_cast<__half2*>(&tu.y));
    float2 s0 = __half22float2(*reinterpret_cast<__half2*>(&su.x));
    float2 s1 = __half22float2(*reinterpret_cast<__half2*>(&su.y));
    float2 a0 = __half22float2(*reinterpret_cast<__half2*>(&au.x));
    float2 a1 = __half22float2(*reinterpret_cast<__half2*>(&au.y));
    float4 y;
    y.x = fmaf(s0.x, a0.x, t0.x) + xv.x;
    y.y = fmaf(s0.y, a0.y, t0.y) + xv.y;
    y.z = fmaf(s1.x, a1.x, t1.x) + xv.z;
    y.w = fmaf(s1.y, a1.y, t1.y) + xv.w;

    float s  = y.x + y.y + y.z + y.w;
    float sq = y.x*y.x + y.y*y.y + y.z*y.z + y.w*y.w;
    #pragma unroll
    for (int o = 16; o; o >>= 1) {
        s  += __shfl_down_sync(0xffffffffu, s,  o);
        sq += __shfl_down_sync(0xffffffffu, sq, o);
    }
    __shared__ float rs[8], rq[8];
    int warp = threadIdx.x >> 5, lane = threadIdx.x & 31;
    if (lane == 0) { rs[warp] = s; rq[warp] = sq; }
    __syncthreads();
    int w0 = half*4;
    float ts = rs[w0]+rs[w0+1]+rs[w0+2]+rs[w0+3];
    float tq = rq[w0]+rq[w0+1]+rq[w0+2]+rq[w0+3];
    float mu  = ts * (1.0f/Cdim);
    float var = tq * (1.0f/Cdim) - mu*mu;
    float r = rsqrtf(var + 1e-5f);

    float4 g = *reinterpret_cast<const float4*>(&gamma[i*4]);
    float4 bb= *reinterpret_cast<const float4*>(&beta[i*4]);
    float4 o4;
    o4.x = (y.x-mu)*r*g.x + bb.x;
    o4.y = (y.y-mu)*r*g.y + bb.y;
    o4.z = (y.z-mu)*r*g.z + bb.z;
    o4.w = (y.w-mu)*r*g.w + bb.w;
    *reinterpret_cast<float4*>(&out[bse]) = o4;
}

// ===================== launch ===============================================
extern "C" void kernel_launch(void* const* d_in, const int* in_sizes, int n_in,
                              void* d_out, int out_size) {
    const float* x     = (const float*)d_in[0];
    const float* tw    = (const float*)d_in[1];
    const float* tb    = (const float*)d_in[2];
    const float* sw    = (const float*)d_in[3];
    const float* sb    = (const float*)d_in[4];
    const float* slw   = (const float*)d_in[5];
    const float* slb   = (const float*)d_in[6];
    const float* cheby = (const float*)d_in[7];
    const float* hw1   = (const float*)d_in[8];
    const float* hb1   = (const float*)d_in[9];
    const float* hw2   = (const float*)d_in[10];
    const float* hb2   = (const float*)d_in[11];
    const float* amp_w = (const float*)d_in[12];
    const float* amp_b = (const float*)d_in[13];
    const float* wav_w = (const float*)d_in[14];
    const float* gamma = (const float*)d_in[15];
    const float* beta  = (const float*)d_in[16];
    float* out = (float*)d_out;

    cudaFuncSetAttribute(gemm_kernel, cudaFuncAttributeMaxDynamicSharedMemorySize, SMEM_GEMM);

    prep_all<<<2049, 256>>>(cheby, wav_w, amp_w);
    decomp_kernel<<<(SEG*Bdim*Cdim)/256, 256>>>(x, tw, tb, sw, sb);   // 1024 blocks
    hyper_pool<<<Bdim, 512>>>(slw, slb);
    hyper_mm<<<dim3(4, Bdim, 8), 256>>>(hw1);
    hyper_psi<<<Bdim, 256>>>(hw2, hb2, hb1);
    gemm_kernel<<<dim3(4, Mrows/128, 2), 256, SMEM_GEMM>>>(0, nullptr);
    gemm_kernel<<<dim3(4, Mrows/128, 1), 256, SMEM_GEMM>>>(2, amp_b);
    epilogue_kernel<<<Mrows/2, 256>>>(x, gamma, beta, out);
}

// round 15
// speedup vs baseline: 1.2149x; 1.0112x over previous
#include <cuda_runtime.h>
#include <cuda_fp16.h>
#include <cstdint>
#include <math.h>

#define Bdim 16
#define Tdim 1024
#define Cdim 512
#define Kma  25
#define NWv  4
#define Mrows (Bdim*Tdim)   // 16384
#define SEG  32
#define SEGLEN (Tdim/SEG)   // 32

// ===================== scratch ==============================================
__device__ __half g_Ac16[Mrows*3*Cdim];   // cheby basis A, [m][k=(d-1)*512+c]
__device__ __half g_sA16[Mrows*Cdim];     // spike_ctx fp16 (wavelet A base)
__device__ __half g_Aa16[Mrows*Cdim];     // tout fp16 (amp A + epilogue trend)
__device__ __half g_s16 [Mrows*Cdim];     // spike_out fp16
__device__ __half g_a16 [Mrows*Cdim];     // amp_scale fp16
__device__ float  g_bias0[Cdim];
__device__ float  g_Spart[SEG][Bdim*Cdim];
__device__ float  g_tr0[Bdim*Cdim];
__device__ float  g_trN[Bdim*Cdim];
__device__ float  g_h  [Bdim*2*Cdim];
__device__ float  g_hacc[Bdim*Cdim];      // pre-activation h1 accumulator
__device__ float  g_wp [Bdim*2*NWv];      // [b][w*2 + {0:da,1:db}]
__device__ int    g_tick[2];              // persistent-GEMM work tickets
// weights transposed to [o][k], fp16
__device__ __half g_Wc16[Cdim*3*Cdim];
__device__ __half g_Ww16[Cdim*NWv*Cdim];
__device__ __half g_Wa16[Cdim*Cdim];

// ===================== helpers ==============================================
__device__ __forceinline__ uint32_t smem_u32(const void* p) {
    uint32_t a;
    asm("{ .reg .u64 t; cvta.to.shared.u64 t, %1; cvt.u32.u64 %0, t; }" : "=r"(a) : "l"(p));
    return a;
}
__device__ __forceinline__ void cp16(uint32_t dst, const void* src) {
    asm volatile("cp.async.cg.shared.global [%0], [%1], 16;" :: "r"(dst), "l"(src));
}
__device__ __forceinline__ void cp_commit() { asm volatile("cp.async.commit_group;"); }
template<int N> __device__ __forceinline__ void cp_wait() {
    asm volatile("cp.async.wait_group %0;" :: "n"(N));
}
__device__ __forceinline__ void ldmx4(uint32_t addr, uint32_t* r) {
    asm volatile("ldmatrix.sync.aligned.m8n8.x4.shared.b16 {%0,%1,%2,%3}, [%4];"
        : "=r"(r[0]), "=r"(r[1]), "=r"(r[2]), "=r"(r[3]) : "r"(addr));
}
__device__ __forceinline__ void mma16816(float* c, const uint32_t* a, const uint32_t* b) {
    asm volatile("mma.sync.aligned.m16n8k16.row.col.f32.f16.f16.f32 "
        "{%0,%1,%2,%3}, {%4,%5,%6,%7}, {%8,%9}, {%0,%1,%2,%3};"
        : "+f"(c[0]), "+f"(c[1]), "+f"(c[2]), "+f"(c[3])
        : "r"(a[0]), "r"(a[1]), "r"(a[2]), "r"(a[3]), "r"(b[0]), "r"(b[1]));
}
__device__ __forceinline__ uint32_t hmul2u(uint32_t a, uint32_t b) {
    __half2 r = __hmul2(*reinterpret_cast<__half2*>(&a), *reinterpret_cast<__half2*>(&b));
    return *reinterpret_cast<uint32_t*>(&r);
}

// ===================== K0: fused weight prep ================================
__global__ void prep_all(const float* __restrict__ cheby,
                         const float* __restrict__ wav_w,
                         const float* __restrict__ amp_w) {
    int bx = blockIdx.x;
    int tx = threadIdx.x & 31, ty = threadIdx.x >> 5;   // 32 x 8

    if (bx == 2048) {
        for (int o = threadIdx.x; o < Cdim; o += 256) {
            float s = 0.f;
            for (int c = 0; c < Cdim; ++c) s += cheby[(c*Cdim + o)*4];
            g_bias0[o] = s;
        }
        if (threadIdx.x < 2) g_tick[threadIdx.x] = 0;   // reset work tickets
        return;
    }

    const float* src; __half* dst; int Ktot, kb, ob, mode;
    if (bx < 768)       { mode = 0; src = cheby; dst = g_Wc16; Ktot = 3*Cdim;
                          kb = (bx % 48)*32;  ob = (bx / 48)*32; }
    else if (bx < 1792) { mode = 1; src = wav_w; dst = g_Ww16; Ktot = NWv*Cdim;
                          int i = bx - 768;  kb = (i % 64)*32; ob = (i / 64)*32; }
    else                { mode = 2; src = amp_w; dst = g_Wa16; Ktot = Cdim;
                          int i = bx - 1792; kb = (i % 16)*32; ob = (i / 16)*32; }

    __shared__ float tile[32][33];
    #pragma unroll
    for (int s = 0; s < 32; s += 8) {
        int k = kb + ty + s, o = ob + tx;
        float v;
        if (mode == 0) { int d = k >> 9, c = k & 511; v = src[(c*Cdim + o)*4 + d + 1]; }
        else           { v = src[(size_t)k*Cdim + o]; }
        tile[ty+s][tx] = v;
    }
    __syncthreads();
    #pragma unroll
    for (int s = 0; s < 32; s += 8) {
        int o = ob + ty + s, k = kb + tx;
        dst[(size_t)o*Ktot + k] = __float2half_rn(tile[tx][ty+s]);
    }
}

// ===================== K1: fused decomposition (scalar, SEG=32) =============
__global__ void decomp_kernel(const float* __restrict__ x,
                              const float* __restrict__ tw, const float* __restrict__ tb,
                              const float* __restrict__ sw, const float* __restrict__ sb) {
    int idx = blockIdx.x*blockDim.x + threadIdx.x;      // 262144 threads
    int c   = idx & (Cdim-1);
    int tmp = idx >> 9;
    int b   = tmp & (Bdim-1);
    int seg = tmp >> 4;
    const float* xb = x + (size_t)b*Tdim*Cdim + c;
    const float inv = 1.0f/(float)Kma;
    float w0t=tw[c*3+0], w1t=tw[c*3+1], w2t=tw[c*3+2], btc=tb[c];
    float w0s=sw[c*3+0], w1s=sw[c*3+1], w2s=sw[c*3+2], bsc=sb[c];

    int t0 = seg*SEGLEN, t1 = t0 + SEGLEN;
    float ws = 0.f;
    int tref = (seg==0) ? 0 : (t0-1);
    #pragma unroll 5
    for (int j = tref-(Kma-1); j <= tref; ++j) ws += xb[max(j,0)*Cdim];

    float tr_m1, tr_c, x_m1, x_c;
    if (seg == 0) {
        tr_c = ws*inv; tr_m1 = tr_c;
        x_c  = xb[0];  x_m1  = x_c;
    } else {
        tr_m1 = ws*inv;
        x_m1  = xb[(t0-1)*Cdim];
        ws   += xb[t0*Cdim] - xb[max(t0-Kma,0)*Cdim];
        tr_c  = ws*inv;
        x_c   = xb[t0*Cdim];
    }

    float Ssum = 0.f;
    #pragma unroll 4
    for (int t = t0; t < t1; ++t) {
        Ssum += tr_c;
        float tr_p, x_p;
        if (t+1 < Tdim) {
            x_p = xb[(t+1)*Cdim];
            ws += x_p - xb[max(t+1-Kma,0)*Cdim];
            tr_p = ws*inv;
        } else { x_p = x_c; tr_p = tr_c; }

        int m = b*Tdim + t;
        float tctx = fmaf(tr_m1,w0t, fmaf(tr_c,w1t, fmaf(tr_p,w2t, btc)));
        float xt = tanhf(tctx);
        float d2 = fmaf(2.f*xt, xt, -1.f);
        float d3 = xt * fmaf(4.f*xt, xt, -3.f);
        size_t arow = (size_t)m*(3*Cdim) + c;
        g_Ac16[arow]          = __float2half_rn(xt);
        g_Ac16[arow + Cdim]   = __float2half_rn(d2);
        g_Ac16[arow + 2*Cdim] = __float2half_rn(d3);

        float sm1 = x_m1-tr_m1, sc = x_c-tr_c, spp = x_p-tr_p;
        float sctx = fmaf(sm1,w0s, fmaf(sc,w1s, fmaf(spp,w2s, bsc)));
        g_sA16[(size_t)m*Cdim + c] = __float2half_rn(sctx);

        if (t == 0)      g_tr0[b*Cdim+c] = tr_c;
        if (t == Tdim-1) g_trN[b*Cdim+c] = tr_c;
        tr_m1 = tr_c; tr_c = tr_p; x_m1 = x_c; x_c = x_p;
    }
    g_Spart[seg][b*Cdim+c] = Ssum;
}

// ===================== K2: hypernetwork (3 kernels) =========================
__global__ void hyper_pool(const float* __restrict__ slw, const float* __restrict__ slb) {
    int b = blockIdx.x, c = threadIdx.x;   // 16 x 512
    g_hacc[b*Cdim + c] = 0.f;              // zero the split-K accumulator
    float S = 0.f;
    #pragma unroll
    for (int s = 0; s < SEG; ++s) S += g_Spart[s][b*Cdim+c];
    float tr0 = g_tr0[b*Cdim+c], trN = g_trN[b*Cdim+c];
    float a0 = slw[c*3+0], a1 = slw[c*3+1], a2 = slw[c*3+2];
    float sp = (a0*(S + tr0 - trN) + a1*S + a2*(S - tr0 + trN)) * (1.0f/Tdim) + slb[c];
    g_h[b*2*Cdim + c]        = sp;
    g_h[b*2*Cdim + Cdim + c] = S * (1.0f/Tdim);
}

// split-K: grid (4, 16, 8) x 256; block (cx,b,ks) does k in [ks*128, ks*128+128)
__global__ void hyper_mm(const float* __restrict__ w1) {
    int b = blockIdx.y, ks = blockIdx.z;
    int col = blockIdx.x*128 + (threadIdx.x & 127);
    int kh  = threadIdx.x >> 7;          // 0/1 -> 64-k half
    __shared__ float hs[128];
    if (threadIdx.x < 128) hs[threadIdx.x] = g_h[b*2*Cdim + ks*128 + threadIdx.x];
    __syncthreads();
    const float* wp = w1 + (size_t)(ks*128 + kh*64)*Cdim + col;
    const float* hp = hs + kh*64;
    float a0=0.f, a1=0.f, a2=0.f, a3=0.f;
    #pragma unroll 4
    for (int i = 0; i < 64; i += 4) {
        a0 = fmaf(hp[i+0], wp[(i+0)*Cdim], a0);
        a1 = fmaf(hp[i+1], wp[(i+1)*Cdim], a1);
        a2 = fmaf(hp[i+2], wp[(i+2)*Cdim], a2);
        a3 = fmaf(hp[i+3], wp[(i+3)*Cdim], a3);
    }
    atomicAdd(&g_hacc[b*Cdim + col], (a0+a1)+(a2+a3));
}

__global__ void hyper_psi(const float* __restrict__ w2, const float* __restrict__ b2,
                          const float* __restrict__ b1) {
    int b = blockIdx.x;
    int j = threadIdx.x;                      // 256
    int warp = j >> 5, lane = j & 31;
    __shared__ float params_s[2*NWv];
    if (warp < 2*NWv) {
        float v = 0.f;
        for (int jj = lane; jj < Cdim; jj += 32) {
            float hv = g_hacc[b*Cdim + jj] + b1[jj];
            hv = hv / (1.f + expf(-hv));      // silu
            v = fmaf(hv, w2[jj*(2*NWv) + warp], v);
        }
        #pragma unroll
        for (int o = 16; o; o >>= 1) v += __shfl_down_sync(0xffffffffu, v, o);
        if (lane == 0) params_s[warp] = v + b2[warp];
    }
    __syncthreads();
    if (j < NWv) {
        float a = params_s[j*2+0], bb = params_s[j*2+1];
        g_wp[b*2*NWv + j*2 + 0] = ((a > 20.f) ? a : log1pf(expf(a))) + 0.01f;
        g_wp[b*2*NWv + j*2 + 1] = (float)Tdim / (1.f + expf(-bb));
    }
}

// ===================== persistent fp16 mma GEMM (work-stealing) =============
// which 0: 1024 tiles — tile<512: wavelet(mode1), else cheby(mode0)
// which 1:  512 tiles — amp(mode2)
#define SPADH 40
#define TO_B  (128*SPADH*2)            // 10240 B
#define STG_BYTES (2*128*SPADH*2)      // 20480 B
#define NSTAGE 4
#define SMEM_GEMM (NSTAGE*STG_BYTES)   // 81920 B  (2 CTAs = 160KB)

__global__ __launch_bounds__(256, 2)
void gemm_kernel(int which, int ntiles, const float* __restrict__ ampb) {
    extern __shared__ char smem[];
    uint32_t sbase = smem_u32(smem);
    __shared__ int s_tile;
    int tid = threadIdx.x, lane = tid & 31, wid = tid >> 5;
    int wm = wid >> 2, wn = wid & 3;

    const uint32_t aRowSel = lane & 15;
    const uint32_t aColSel = ((lane >> 4) & 1)*8;
    const uint32_t bRowSel = ((lane >> 4) & 1)*8 + (lane & 7);
    const uint32_t bColSel = ((lane >> 3) & 1)*8;

    for (;;) {
        if (tid == 0) s_tile = atomicAdd(&g_tick[which], 1);
        __syncthreads();
        int tile = s_tile;
        __syncthreads();
        if (tile >= ntiles) return;

        int mode, m0, n0;
        if (which == 0) {
            mode = (tile < 512) ? 1 : 0;
            int t = tile & 511;
            n0 = (t & 3)*128; m0 = (t >> 2)*128;
        } else {
            mode = 2;
            n0 = (tile & 3)*128; m0 = (tile >> 2)*128;
        }

        const __half *Ag, *Bg; int Ktot;
        if (mode == 0)      { Ag = g_Ac16; Bg = g_Wc16; Ktot = 3*Cdim; }
        else if (mode == 1) { Ag = g_sA16; Bg = g_Ww16; Ktot = NWv*Cdim; }
        else                { Ag = g_Aa16; Bg = g_Wa16; Ktot = Cdim; }
        const int NKB = Ktot / 32;
        const int AK  = (mode == 1) ? Cdim : Ktot;

        int r = tid >> 1, hf_ = tid & 1;
        const __half* gA = Ag + (size_t)(m0 + r)*AK + hf_*16;
        const __half* gB = Bg + (size_t)(n0 + r)*Ktot + hf_*16;
        uint32_t sAd = sbase + (uint32_t)(r*SPADH + hf_*16)*2;
        uint32_t sBd = sAd + TO_B;

        auto issue = [&](int kb) {
            uint32_t so = (uint32_t)(kb & (NSTAGE-1))*STG_BYTES;
            int ak = (mode == 1) ? (kb & 15)*32 : kb*32;
            const __half* pa = gA + ak;
            const __half* pb = gB + (size_t)kb*32;
            cp16(sAd + so, pa); cp16(sAd + so + 16, pa + 8);
            cp16(sBd + so, pb); cp16(sBd + so + 16, pb + 8);
        };

        float acc[4][4][4];
        #pragma unroll
        for (int i = 0; i < 4; ++i)
            #pragma unroll
            for (int j = 0; j < 4; ++j)
                #pragma unroll
                for (int q = 0; q < 4; ++q) acc[i][j][q] = 0.f;

        uint32_t ph1[4], ph2[4];
        const int bIdx = m0 >> 10;
        const int tbase = m0 & (Tdim-1);

        const int NP = (NSTAGE-1 < NKB) ? NSTAGE-1 : NKB;
        for (int s = 0; s < NP; ++s) { issue(s); cp_commit(); }

        for (int kb = 0; kb < NKB; ++kb) {
            if (mode == 1 && (kb & 15) == 0) {
                int w = kb >> 4;
                float da = g_wp[bIdx*8 + w*2], dbv = g_wp[bIdx*8 + w*2 + 1];
                #pragma unroll
                for (int mt = 0; mt < 4; ++mt) {
                    float t1 = (float)(tbase + wm*64 + mt*16 + (int)(lane >> 2));
                    float z = (t1 - dbv)/da, z2 = z*z;
                    float p1 = (1.f - z2)*expf(-0.5f*z2);
                    float t2 = t1 + 8.f;
                    z = (t2 - dbv)/da; z2 = z*z;
                    float p2 = (1.f - z2)*expf(-0.5f*z2);
                    __half2 h1v = __half2half2(__float2half_rn(p1));
                    __half2 h2v = __half2half2(__float2half_rn(p2));
                    ph1[mt] = *reinterpret_cast<uint32_t*>(&h1v);
                    ph2[mt] = *reinterpret_cast<uint32_t*>(&h2v);
                }
            }
            cp_wait<NSTAGE-2>();
            __syncthreads();

            uint32_t sb = sbase + (uint32_t)(kb & (NSTAGE-1))*STG_BYTES;
            #pragma unroll
            for (int kk = 0; kk < 2; ++kk) {
                uint32_t kO = kk*16;
                uint32_t aF[4][4], bF[4][2];
                #pragma unroll
                for (int mt = 0; mt < 4; ++mt) {
                    uint32_t row = wm*64 + mt*16 + aRowSel;
                    ldmx4(sb + (row*SPADH + kO + aColSel)*2, aF[mt]);
                }
                if (mode == 1) {
                    #pragma unroll
                    for (int mt = 0; mt < 4; ++mt) {
                        aF[mt][0] = hmul2u(aF[mt][0], ph1[mt]);
                        aF[mt][2] = hmul2u(aF[mt][2], ph1[mt]);
                        aF[mt][1] = hmul2u(aF[mt][1], ph2[mt]);
                        aF[mt][3] = hmul2u(aF[mt][3], ph2[mt]);
                    }
                }
                #pragma unroll
                for (int p = 0; p < 2; ++p) {
                    uint32_t row = wn*32 + p*16 + bRowSel;
                    uint32_t r4[4];
                    ldmx4(sb + TO_B + (row*SPADH + kO + bColSel)*2, r4);
                    bF[p*2+0][0] = r4[0]; bF[p*2+0][1] = r4[1];
                    bF[p*2+1][0] = r4[2]; bF[p*2+1][1] = r4[3];
                }
                #pragma unroll
                for (int mt = 0; mt < 4; ++mt)
                    #pragma unroll
                    for (int nt = 0; nt < 4; ++nt)
                        mma16816(acc[mt][nt], aF[mt], bF[nt]);
            }
            if (kb + NSTAGE-1 < NKB) issue(kb + NSTAGE-1);
            cp_commit();
        }

        // ---- tile epilogue ----
        const int cRow = lane >> 2, cCol2 = (lane & 3)*2;
        #pragma unroll
        for (int mt = 0; mt < 4; ++mt) {
            #pragma unroll
            for (int nt = 0; nt < 4; ++nt) {
                int col = n0 + wn*32 + nt*8 + cCol2;
                float v0 = acc[mt][nt][0], v1 = acc[mt][nt][1];
                float v2 = acc[mt][nt][2], v3 = acc[mt][nt][3];
                int row = m0 + wm*64 + mt*16 + cRow;
                if (mode == 0) {
                    float b0 = g_bias0[col], b1 = g_bias0[col+1];
                    v0 += b0; v1 += b1; v2 += b0; v3 += b1;
                    *reinterpret_cast<__half2*>(&g_Aa16[(size_t)row*Cdim + col]) =
                        __floats2half2_rn(v0, v1);
                    *reinterpret_cast<__half2*>(&g_Aa16[(size_t)(row+8)*Cdim + col]) =
                        __floats2half2_rn(v2, v3);
                } else if (mode == 1) {
                    *reinterpret_cast<__half2*>(&g_s16[(size_t)row*Cdim + col]) =
                        __floats2half2_rn(v0, v1);
                    *reinterpret_cast<__half2*>(&g_s16[(size_t)(row+8)*Cdim + col]) =
                        __floats2half2_rn(v2, v3);
                } else {
                    float b0 = ampb[col], b1 = ampb[col+1];
                    v0 = 2.f/(1.f+expf(-(v0+b0))); v1 = 2.f/(1.f+expf(-(v1+b1)));
                    v2 = 2.f/(1.f+expf(-(v2+b0))); v3 = 2.f/(1.f+expf(-(v3+b1)));
                    *reinterpret_cast<__half2*>(&g_a16[(size_t)row*Cdim + col]) =
                        __floats2half2_rn(v0, v1);
                    *reinterpret_cast<__half2*>(&g_a16[(size_t)(row+8)*Cdim + col]) =
                        __floats2half2_rn(v2, v3);
                }
            }
        }
        __syncthreads();   // smem safe for next tile's prologue
    }
}

// ===================== K5: gate + residual + LayerNorm (2 rows/block) =======
__global__ void epilogue_kernel(const float* __restrict__ x,
                                const float* __restrict__ gamma,
                                const float* __restrict__ beta,
                                float* __restrict__ out) {
    int half = threadIdx.x >> 7;          // 0/1 -> row within block
    int i    = threadIdx.x & 127;         // 128 threads per row
    int m    = blockIdx.x*2 + half;
    size_t bse = (size_t)m*Cdim + i*4;
    float4 xv = *reinterpret_cast<const float4*>(&x[bse]);
    uint2 tu = *reinterpret_cast<const uint2*>(&g_Aa16[bse]);
    uint2 su = *reinterpret_cast<const uint2*>(&g_s16[bse]);
    uint2 au = *reinterpret_cast<const uint2*>(&g_a16[bse]);
    float2 t0 = __half22float2(*reinterpret_cast<__half2*>(&tu.x));
    float2 t1 = __half22float2(*reinterpret_cast<__half2*>(&tu.y));
    float2 s0 = __half22float2(*reinterpret_cast<__half2*>(&su.x));
    float2 s1 = __half22float2(*reinterpret_cast<__half2*>(&su.y));
    float2 a0 = __half22float2(*reinterpret_cast<__half2*>(&au.x));
    float2 a1 = __half22float2(*reinterpret_cast<__half2*>(&au.y));
    float4 y;
    y.x = fmaf(s0.x, a0.x, t0.x) + xv.x;
    y.y = fmaf(s0.y, a0.y, t0.y) + xv.y;
    y.z = fmaf(s1.x, a1.x, t1.x) + xv.z;
    y.w = fmaf(s1.y, a1.y, t1.y) + xv.w;

    float s  = y.x + y.y + y.z + y.w;
    float sq = y.x*y.x + y.y*y.y + y.z*y.z + y.w*y.w;
    #pragma unroll
    for (int o = 16; o; o >>= 1) {
        s  += __shfl_down_sync(0xffffffffu, s,  o);
        sq += __shfl_down_sync(0xffffffffu, sq, o);
    }
    __shared__ float rs[8], rq[8];
    int warp = threadIdx.x >> 5, lane = threadIdx.x & 31;
    if (lane == 0) { rs[warp] = s; rq[warp] = sq; }
    __syncthreads();
    int w0 = half*4;
    float ts = rs[w0]+rs[w0+1]+rs[w0+2]+rs[w0+3];
    float tq = rq[w0]+rq[w0+1]+rq[w0+2]+rq[w0+3];
    float mu  = ts * (1.0f/Cdim);
    float var = tq * (1.0f/Cdim) - mu*mu;
    float r = rsqrtf(var + 1e-5f);

    float4 g = *reinterpret_cast<const float4*>(&gamma[i*4]);
    float4 bb= *reinterpret_cast<const float4*>(&beta[i*4]);
    float4 o4;
    o4.x = (y.x-mu)*r*g.x + bb.x;
    o4.y = (y.y-mu)*r*g.y + bb.y;
    o4.z = (y.z-mu)*r*g.z + bb.z;
    o4.w = (y.w-mu)*r*g.w + bb.w;
    *reinterpret_cast<float4*>(&out[bse]) = o4;
}

// ===================== launch ===============================================
extern "C" void kernel_launch(void* const* d_in, const int* in_sizes, int n_in,
                              void* d_out, int out_size) {
    const float* x     = (const float*)d_in[0];
    const float* tw    = (const float*)d_in[1];
    const float* tb    = (const float*)d_in[2];
    const float* sw    = (const float*)d_in[3];
    const float* sb    = (const float*)d_in[4];
    const float* slw   = (const float*)d_in[5];
    const float* slb   = (const float*)d_in[6];
    const float* cheby = (const float*)d_in[7];
    const float* hw1   = (const float*)d_in[8];
    const float* hb1   = (const float*)d_in[9];
    const float* hw2   = (const float*)d_in[10];
    const float* hb2   = (const float*)d_in[11];
    const float* amp_w = (const float*)d_in[12];
    const float* amp_b = (const float*)d_in[13];
    const float* wav_w = (const float*)d_in[14];
    const float* gamma = (const float*)d_in[15];
    const float* beta  = (const float*)d_in[16];
    float* out = (float*)d_out;

    cudaFuncSetAttribute(gemm_kernel, cudaFuncAttributeMaxDynamicSharedMemorySize, SMEM_GEMM);

    prep_all<<<2049, 256>>>(cheby, wav_w, amp_w);
    decomp_kernel<<<(SEG*Bdim*Cdim)/256, 256>>>(x, tw, tb, sw, sb);   // 1024 blocks
    hyper_pool<<<Bdim, 512>>>(slw, slb);
    hyper_mm<<<dim3(4, Bdim, 8), 256>>>(hw1);
    hyper_psi<<<Bdim, 256>>>(hw2, hb2, hb1);
    gemm_kernel<<<296, 256, SMEM_GEMM>>>(0, 1024, nullptr);   // persistent: wavelet+cheby
    gemm_kernel<<<296, 256, SMEM_GEMM>>>(1, 512,  amp_b);     // persistent: amp
    epilogue_kernel<<<Mrows/2, 256>>>(x, gamma, beta, out);
}

// round 16
// speedup vs baseline: 1.2251x; 1.0085x over previous
#include <cuda_runtime.h>
#include <cuda_fp16.h>
#include <cstdint>
#include <math.h>

#define Bdim 16
#define Tdim 1024
#define Cdim 512
#define Kma  25
#define NWv  4
#define Mrows (Bdim*Tdim)   // 16384
#define SEG  32
#define SEGLEN (Tdim/SEG)   // 32

// ===================== scratch ==============================================
__device__ __half g_Ac16[Mrows*3*Cdim];   // cheby basis A
__device__ __half g_sA16[Mrows*Cdim];     // spike_ctx fp16
__device__ __half g_Aa16[Mrows*Cdim];     // tout fp16
__device__ __half g_s16 [Mrows*Cdim];     // spike_out fp16
__device__ __half g_a16 [Mrows*Cdim];     // amp_scale fp16
__device__ float  g_bias0[Cdim];
__device__ float  g_Spart[SEG][Bdim*Cdim];
__device__ float  g_tr0[Bdim*Cdim];
__device__ float  g_trN[Bdim*Cdim];
__device__ float  g_h  [Bdim*2*Cdim];
__device__ float  g_hacc[Bdim*Cdim];
__device__ float  g_wp [Bdim*2*NWv];
__device__ int    g_tick;                 // persistent-GEMM ticket
__device__ int    g_done[Mrows/128];      // per-m-band cheby completion (4 tiles)
// weights transposed to [o][k], fp16
__device__ __half g_Wc16[Cdim*3*Cdim];
__device__ __half g_Ww16[Cdim*NWv*Cdim];
__device__ __half g_Wa16[Cdim*Cdim];

// ===================== helpers ==============================================
__device__ __forceinline__ uint32_t smem_u32(const void* p) {
    uint32_t a;
    asm("{ .reg .u64 t; cvta.to.shared.u64 t, %1; cvt.u32.u64 %0, t; }" : "=r"(a) : "l"(p));
    return a;
}
__device__ __forceinline__ void cp16(uint32_t dst, const void* src) {
    asm volatile("cp.async.cg.shared.global [%0], [%1], 16;" :: "r"(dst), "l"(src));
}
__device__ __forceinline__ void cp_commit() { asm volatile("cp.async.commit_group;"); }
template<int N> __device__ __forceinline__ void cp_wait() {
    asm volatile("cp.async.wait_group %0;" :: "n"(N));
}
__device__ __forceinline__ void ldmx4(uint32_t addr, uint32_t* r) {
    asm volatile("ldmatrix.sync.aligned.m8n8.x4.shared.b16 {%0,%1,%2,%3}, [%4];"
        : "=r"(r[0]), "=r"(r[1]), "=r"(r[2]), "=r"(r[3]) : "r"(addr));
}
__device__ __forceinline__ void mma16816(float* c, const uint32_t* a, const uint32_t* b) {
    asm volatile("mma.sync.aligned.m16n8k16.row.col.f32.f16.f16.f32 "
        "{%0,%1,%2,%3}, {%4,%5,%6,%7}, {%8,%9}, {%0,%1,%2,%3};"
        : "+f"(c[0]), "+f"(c[1]), "+f"(c[2]), "+f"(c[3])
        : "r"(a[0]), "r"(a[1]), "r"(a[2]), "r"(a[3]), "r"(b[0]), "r"(b[1]));
}
__device__ __forceinline__ uint32_t hmul2u(uint32_t a, uint32_t b) {
    __half2 r = __hmul2(*reinterpret_cast<__half2*>(&a), *reinterpret_cast<__half2*>(&b));
    return *reinterpret_cast<uint32_t*>(&r);
}

// ===================== K0: fused weight prep ================================
__global__ void prep_all(const float* __restrict__ cheby,
                         const float* __restrict__ wav_w,
                         const float* __restrict__ amp_w) {
    int bx = blockIdx.x;
    int tx = threadIdx.x & 31, ty = threadIdx.x >> 5;   // 32 x 8

    if (bx == 2048) {
        for (int o = threadIdx.x; o < Cdim; o += 256) {
            float s = 0.f;
            for (int c = 0; c < Cdim; ++c) s += cheby[(c*Cdim + o)*4];
            g_bias0[o] = s;
        }
        if (threadIdx.x == 0) g_tick = 0;
        if (threadIdx.x < Mrows/128) g_done[threadIdx.x] = 0;
        return;
    }

    const float* src; __half* dst; int Ktot, kb, ob, mode;
    if (bx < 768)       { mode = 0; src = cheby; dst = g_Wc16; Ktot = 3*Cdim;
                          kb = (bx % 48)*32;  ob = (bx / 48)*32; }
    else if (bx < 1792) { mode = 1; src = wav_w; dst = g_Ww16; Ktot = NWv*Cdim;
                          int i = bx - 768;  kb = (i % 64)*32; ob = (i / 64)*32; }
    else                { mode = 2; src = amp_w; dst = g_Wa16; Ktot = Cdim;
                          int i = bx - 1792; kb = (i % 16)*32; ob = (i / 16)*32; }

    __shared__ float tile[32][33];
    #pragma unroll
    for (int s = 0; s < 32; s += 8) {
        int k = kb + ty + s, o = ob + tx;
        float v;
        if (mode == 0) { int d = k >> 9, c = k & 511; v = src[(c*Cdim + o)*4 + d + 1]; }
        else           { v = src[(size_t)k*Cdim + o]; }
        tile[ty+s][tx] = v;
    }
    __syncthreads();
    #pragma unroll
    for (int s = 0; s < 32; s += 8) {
        int o = ob + ty + s, k = kb + tx;
        dst[(size_t)o*Ktot + k] = __float2half_rn(tile[tx][ty+s]);
    }
}

// ===================== K1: fused decomposition (scalar, SEG=32) =============
__global__ void decomp_kernel(const float* __restrict__ x,
                              const float* __restrict__ tw, const float* __restrict__ tb,
                              const float* __restrict__ sw, const float* __restrict__ sb) {
    int idx = blockIdx.x*blockDim.x + threadIdx.x;      // 262144 threads
    int c   = idx & (Cdim-1);
    int tmp = idx >> 9;
    int b   = tmp & (Bdim-1);
    int seg = tmp >> 4;
    const float* xb = x + (size_t)b*Tdim*Cdim + c;
    const float inv = 1.0f/(float)Kma;
    float w0t=tw[c*3+0], w1t=tw[c*3+1], w2t=tw[c*3+2], btc=tb[c];
    float w0s=sw[c*3+0], w1s=sw[c*3+1], w2s=sw[c*3+2], bsc=sb[c];

    int t0 = seg*SEGLEN, t1 = t0 + SEGLEN;
    float ws = 0.f;
    int tref = (seg==0) ? 0 : (t0-1);
    #pragma unroll 5
    for (int j = tref-(Kma-1); j <= tref; ++j) ws += xb[max(j,0)*Cdim];

    float tr_m1, tr_c, x_m1, x_c;
    if (seg == 0) {
        tr_c = ws*inv; tr_m1 = tr_c;
        x_c  = xb[0];  x_m1  = x_c;
    } else {
        tr_m1 = ws*inv;
        x_m1  = xb[(t0-1)*Cdim];
        ws   += xb[t0*Cdim] - xb[max(t0-Kma,0)*Cdim];
        tr_c  = ws*inv;
        x_c   = xb[t0*Cdim];
    }

    float Ssum = 0.f;
    #pragma unroll 4
    for (int t = t0; t < t1; ++t) {
        Ssum += tr_c;
        float tr_p, x_p;
        if (t+1 < Tdim) {
            x_p = xb[(t+1)*Cdim];
            ws += x_p - xb[max(t+1-Kma,0)*Cdim];
            tr_p = ws*inv;
        } else { x_p = x_c; tr_p = tr_c; }

        int m = b*Tdim + t;
        float tctx = fmaf(tr_m1,w0t, fmaf(tr_c,w1t, fmaf(tr_p,w2t, btc)));
        float xt = tanhf(tctx);
        float d2 = fmaf(2.f*xt, xt, -1.f);
        float d3 = xt * fmaf(4.f*xt, xt, -3.f);
        size_t arow = (size_t)m*(3*Cdim) + c;
        g_Ac16[arow]          = __float2half_rn(xt);
        g_Ac16[arow + Cdim]   = __float2half_rn(d2);
        g_Ac16[arow + 2*Cdim] = __float2half_rn(d3);

        float sm1 = x_m1-tr_m1, sc = x_c-tr_c, spp = x_p-tr_p;
        float sctx = fmaf(sm1,w0s, fmaf(sc,w1s, fmaf(spp,w2s, bsc)));
        g_sA16[(size_t)m*Cdim + c] = __float2half_rn(sctx);

        if (t == 0)      g_tr0[b*Cdim+c] = tr_c;
        if (t == Tdim-1) g_trN[b*Cdim+c] = tr_c;
        tr_m1 = tr_c; tr_c = tr_p; x_m1 = x_c; x_c = x_p;
    }
    g_Spart[seg][b*Cdim+c] = Ssum;
}

// ===================== K2: hypernetwork (3 kernels) =========================
__global__ void hyper_pool(const float* __restrict__ slw, const float* __restrict__ slb) {
    int b = blockIdx.x, c = threadIdx.x;   // 16 x 512
    g_hacc[b*Cdim + c] = 0.f;
    float S = 0.f;
    #pragma unroll
    for (int s = 0; s < SEG; ++s) S += g_Spart[s][b*Cdim+c];
    float tr0 = g_tr0[b*Cdim+c], trN = g_trN[b*Cdim+c];
    float a0 = slw[c*3+0], a1 = slw[c*3+1], a2 = slw[c*3+2];
    float sp = (a0*(S + tr0 - trN) + a1*S + a2*(S - tr0 + trN)) * (1.0f/Tdim) + slb[c];
    g_h[b*2*Cdim + c]        = sp;
    g_h[b*2*Cdim + Cdim + c] = S * (1.0f/Tdim);
}

__global__ void hyper_mm(const float* __restrict__ w1) {
    int b = blockIdx.y, ks = blockIdx.z;
    int col = blockIdx.x*128 + (threadIdx.x & 127);
    int kh  = threadIdx.x >> 7;
    __shared__ float hs[128];
    if (threadIdx.x < 128) hs[threadIdx.x] = g_h[b*2*Cdim + ks*128 + threadIdx.x];
    __syncthreads();
    const float* wp = w1 + (size_t)(ks*128 + kh*64)*Cdim + col;
    const float* hp = hs + kh*64;
    float a0=0.f, a1=0.f, a2=0.f, a3=0.f;
    #pragma unroll 4
    for (int i = 0; i < 64; i += 4) {
        a0 = fmaf(hp[i+0], wp[(i+0)*Cdim], a0);
        a1 = fmaf(hp[i+1], wp[(i+1)*Cdim], a1);
        a2 = fmaf(hp[i+2], wp[(i+2)*Cdim], a2);
        a3 = fmaf(hp[i+3], wp[(i+3)*Cdim], a3);
    }
    atomicAdd(&g_hacc[b*Cdim + col], (a0+a1)+(a2+a3));
}

__global__ void hyper_psi(const float* __restrict__ w2, const float* __restrict__ b2,
                          const float* __restrict__ b1) {
    int b = blockIdx.x;
    int j = threadIdx.x;                      // 256
    int warp = j >> 5, lane = j & 31;
    __shared__ float params_s[2*NWv];
    if (warp < 2*NWv) {
        float v = 0.f;
        for (int jj = lane; jj < Cdim; jj += 32) {
            float hv = g_hacc[b*Cdim + jj] + b1[jj];
            hv = hv / (1.f + expf(-hv));
            v = fmaf(hv, w2[jj*(2*NWv) + warp], v);
        }
        #pragma unroll
        for (int o = 16; o; o >>= 1) v += __shfl_down_sync(0xffffffffu, v, o);
        if (lane == 0) params_s[warp] = v + b2[warp];
    }
    __syncthreads();
    if (j < NWv) {
        float a = params_s[j*2+0], bb = params_s[j*2+1];
        g_wp[b*2*NWv + j*2 + 0] = ((a > 20.f) ? a : log1pf(expf(a))) + 0.01f;
        g_wp[b*2*NWv + j*2 + 1] = (float)Tdim / (1.f + expf(-bb));
    }
}

// ===================== unified persistent fp16 mma GEMM =====================
// 1536 tiles: [0,512) wavelet  [512,1024) cheby  [1024,1536) amp (gated)
#define SPADH 40
#define TO_B  (128*SPADH*2)
#define STG_BYTES (2*128*SPADH*2)
#define NSTAGE 4
#define SMEM_GEMM (NSTAGE*STG_BYTES)

__global__ __launch_bounds__(256, 2)
void gemm_kernel(const float* __restrict__ ampb) {
    extern __shared__ char smem[];
    uint32_t sbase = smem_u32(smem);
    __shared__ int s_tile;
    int tid = threadIdx.x, lane = tid & 31, wid = tid >> 5;
    int wm = wid >> 2, wn = wid & 3;

    const uint32_t aRowSel = lane & 15;
    const uint32_t aColSel = ((lane >> 4) & 1)*8;
    const uint32_t bRowSel = ((lane >> 4) & 1)*8 + (lane & 7);
    const uint32_t bColSel = ((lane >> 3) & 1)*8;

    for (;;) {
        if (tid == 0) s_tile = atomicAdd(&g_tick, 1);
        __syncthreads();
        int tile = s_tile;
        __syncthreads();
        if (tile >= 1536) return;

        int mode, t;
        if (tile < 512)       { mode = 1; t = tile; }
        else if (tile < 1024) { mode = 0; t = tile - 512; }
        else                  { mode = 2; t = tile - 1024; }
        int band = t >> 2;
        int m0 = band*128, n0 = (t & 3)*128;

        if (mode == 2) {                       // wait for band's cheby tiles
            if (tid == 0) {
                volatile int* dp = g_done + band;
                while (*dp < 4) { }
            }
            __syncthreads();
            __threadfence();                   // acquire
        }

        const __half *Ag, *Bg; int Ktot;
        if (mode == 0)      { Ag = g_Ac16; Bg = g_Wc16; Ktot = 3*Cdim; }
        else if (mode == 1) { Ag = g_sA16; Bg = g_Ww16; Ktot = NWv*Cdim; }
        else                { Ag = g_Aa16; Bg = g_Wa16; Ktot = Cdim; }
        const int NKB = Ktot / 32;
        const int AK  = (mode == 1) ? Cdim : Ktot;

        int r = tid >> 1, hf_ = tid & 1;
        const __half* gA = Ag + (size_t)(m0 + r)*AK + hf_*16;
        const __half* gB = Bg + (size_t)(n0 + r)*Ktot + hf_*16;
        uint32_t sAd = sbase + (uint32_t)(r*SPADH + hf_*16)*2;
        uint32_t sBd = sAd + TO_B;

        auto issue = [&](int kb) {
            uint32_t so = (uint32_t)(kb & (NSTAGE-1))*STG_BYTES;
            int ak = (mode == 1) ? (kb & 15)*32 : kb*32;
            const __half* pa = gA + ak;
            const __half* pb = gB + (size_t)kb*32;
            cp16(sAd + so, pa); cp16(sAd + so + 16, pa + 8);
            cp16(sBd + so, pb); cp16(sBd + so + 16, pb + 8);
        };

        float acc[4][4][4];
        #pragma unroll
        for (int i = 0; i < 4; ++i)
            #pragma unroll
            for (int j = 0; j < 4; ++j)
                #pragma unroll
                for (int q = 0; q < 4; ++q) acc[i][j][q] = 0.f;

        uint32_t ph1[4], ph2[4];
        const int bIdx = m0 >> 10;
        const int tbase = m0 & (Tdim-1);

        const int NP = (NSTAGE-1 < NKB) ? NSTAGE-1 : NKB;
        for (int s = 0; s < NP; ++s) { issue(s); cp_commit(); }

        for (int kb = 0; kb < NKB; ++kb) {
            if (mode == 1 && (kb & 15) == 0) {
                int w = kb >> 4;
                float da = g_wp[bIdx*8 + w*2], dbv = g_wp[bIdx*8 + w*2 + 1];
                #pragma unroll
                for (int mt = 0; mt < 4; ++mt) {
                    float t1 = (float)(tbase + wm*64 + mt*16 + (int)(lane >> 2));
                    float z = (t1 - dbv)/da, z2 = z*z;
                    float p1 = (1.f - z2)*expf(-0.5f*z2);
                    float t2 = t1 + 8.f;
                    z = (t2 - dbv)/da; z2 = z*z;
                    float p2 = (1.f - z2)*expf(-0.5f*z2);
                    __half2 h1v = __half2half2(__float2half_rn(p1));
                    __half2 h2v = __half2half2(__float2half_rn(p2));
                    ph1[mt] = *reinterpret_cast<uint32_t*>(&h1v);
                    ph2[mt] = *reinterpret_cast<uint32_t*>(&h2v);
                }
            }
            cp_wait<NSTAGE-2>();
            __syncthreads();

            uint32_t sb = sbase + (uint32_t)(kb & (NSTAGE-1))*STG_BYTES;
            #pragma unroll
            for (int kk = 0; kk < 2; ++kk) {
                uint32_t kO = kk*16;
                uint32_t aF[4][4], bF[4][2];
                #pragma unroll
                for (int mt = 0; mt < 4; ++mt) {
                    uint32_t row = wm*64 + mt*16 + aRowSel;
                    ldmx4(sb + (row*SPADH + kO + aColSel)*2, aF[mt]);
                }
                if (mode == 1) {
                    #pragma unroll
                    for (int mt = 0; mt < 4; ++mt) {
                        aF[mt][0] = hmul2u(aF[mt][0], ph1[mt]);
                        aF[mt][2] = hmul2u(aF[mt][2], ph1[mt]);
                        aF[mt][1] = hmul2u(aF[mt][1], ph2[mt]);
                        aF[mt][3] = hmul2u(aF[mt][3], ph2[mt]);
                    }
                }
                #pragma unroll
                for (int p = 0; p < 2; ++p) {
                    uint32_t row = wn*32 + p*16 + bRowSel;
                    uint32_t r4[4];
                    ldmx4(sb + TO_B + (row*SPADH + kO + bColSel)*2, r4);
                    bF[p*2+0][0] = r4[0]; bF[p*2+0][1] = r4[1];
                    bF[p*2+1][0] = r4[2]; bF[p*2+1][1] = r4[3];
                }
                #pragma unroll
                for (int mt = 0; mt < 4; ++mt)
                    #pragma unroll
                    for (int nt = 0; nt < 4; ++nt)
                        mma16816(acc[mt][nt], aF[mt], bF[nt]);
            }
            if (kb + NSTAGE-1 < NKB) issue(kb + NSTAGE-1);
            cp_commit();
        }

        // ---- tile epilogue ----
        const int cRow = lane >> 2, cCol2 = (lane & 3)*2;
        #pragma unroll
        for (int mt = 0; mt < 4; ++mt) {
            #pragma unroll
            for (int nt = 0; nt < 4; ++nt) {
                int col = n0 + wn*32 + nt*8 + cCol2;
                float v0 = acc[mt][nt][0], v1 = acc[mt][nt][1];
                float v2 = acc[mt][nt][2], v3 = acc[mt][nt][3];
                int row = m0 + wm*64 + mt*16 + cRow;
                if (mode == 0) {
                    float b0 = g_bias0[col], b1 = g_bias0[col+1];
                    v0 += b0; v1 += b1; v2 += b0; v3 += b1;
                    *reinterpret_cast<__half2*>(&g_Aa16[(size_t)row*Cdim + col]) =
                        __floats2half2_rn(v0, v1);
                    *reinterpret_cast<__half2*>(&g_Aa16[(size_t)(row+8)*Cdim + col]) =
                        __floats2half2_rn(v2, v3);
                } else if (mode == 1) {
                    *reinterpret_cast<__half2*>(&g_s16[(size_t)row*Cdim + col]) =
                        __floats2half2_rn(v0, v1);
                    *reinterpret_cast<__half2*>(&g_s16[(size_t)(row+8)*Cdim + col]) =
                        __floats2half2_rn(v2, v3);
                } else {
                    float b0 = ampb[col], b1 = ampb[col+1];
                    v0 = 2.f/(1.f+expf(-(v0+b0))); v1 = 2.f/(1.f+expf(-(v1+b1)));
                    v2 = 2.f/(1.f+expf(-(v2+b0))); v3 = 2.f/(1.f+expf(-(v3+b1)));
                    *reinterpret_cast<__half2*>(&g_a16[(size_t)row*Cdim + col]) =
                        __floats2half2_rn(v0, v1);
                    *reinterpret_cast<__half2*>(&g_a16[(size_t)(row+8)*Cdim + col]) =
                        __floats2half2_rn(v2, v3);
                }
            }
        }
        if (mode == 0) {               // release: band's tout tile done
            __threadfence();
            __syncthreads();
            if (tid == 0) atomicAdd(&g_done[band], 1);
        } else {
            __syncthreads();           // smem safe for next tile
        }
    }
}

// ===================== K5: gate + residual + LayerNorm (2 rows/block) =======
__global__ void epilogue_kernel(const float* __restrict__ x,
                                const float* __restrict__ gamma,
                                const float* __restrict__ beta,
                                float* __restrict__ out) {
    int half = threadIdx.x >> 7;
    int i    = threadIdx.x & 127;
    int m    = blockIdx.x*2 + half;
    size_t bse = (size_t)m*Cdim + i*4;
    float4 xv = *reinterpret_cast<const float4*>(&x[bse]);
    uint2 tu = *reinterpret_cast<const uint2*>(&g_Aa16[bse]);
    uint2 su = *reinterpret_cast<const uint2*>(&g_s16[bse]);
    uint2 au = *reinterpret_cast<const uint2*>(&g_a16[bse]);
    float2 t0 = __half22float2(*reinterpret_cast<__half2*>(&tu.x));
    float2 t1 = __half22float2(*reinterpret_cast<__half2*>(&tu.y));
    float2 s0 = __half22float2(*reinterpret_cast<__half2*>(&su.x));
    float2 s1 = __half22float2(*reinterpret_cast<__half2*>(&su.y));
    float2 a0 = __half22float2(*reinterpret_cast<__half2*>(&au.x));
    float2 a1 = __half22float2(*reinterpret_cast<__half2*>(&au.y));
    float4 y;
    y.x = fmaf(s0.x, a0.x, t0.x) + xv.x;
    y.y = fmaf(s0.y, a0.y, t0.y) + xv.y;
    y.z = fmaf(s1.x, a1.x, t1.x) + xv.z;
    y.w = fmaf(s1.y, a1.y, t1.y) + xv.w;

    float s  = y.x + y.y + y.z + y.w;
    float sq = y.x*y.x + y.y*y.y + y.z*y.z + y.w*y.w;
    #pragma unroll
    for (int o = 16; o; o >>= 1) {
        s  += __shfl_down_sync(0xffffffffu, s,  o);
        sq += __shfl_down_sync(0xffffffffu, sq, o);
    }
    __shared__ float rs[8], rq[8];
    int warp = threadIdx.x >> 5, lane = threadIdx.x & 31;
    if (lane == 0) { rs[warp] = s; rq[warp] = sq; }
    __syncthreads();
    int w0 = half*4;
    float ts = rs[w0]+rs[w0+1]+rs[w0+2]+rs[w0+3];
    float tq = rq[w0]+rq[w0+1]+rq[w0+2]+rq[w0+3];
    float mu  = ts * (1.0f/Cdim);
    float var = tq * (1.0f/Cdim) - mu*mu;
    float r = rsqrtf(var + 1e-5f);

    float4 g = *reinterpret_cast<const float4*>(&gamma[i*4]);
    float4 bb= *reinterpret_cast<const float4*>(&beta[i*4]);
    float4 o4;
    o4.x = (y.x-mu)*r*g.x + bb.x;
    o4.y = (y.y-mu)*r*g.y + bb.y;
    o4.z = (y.z-mu)*r*g.z + bb.z;
    o4.w = (y.w-mu)*r*g.w + bb.w;
    *reinterpret_cast<float4*>(&out[bse]) = o4;
}

// ===================== launch ===============================================
extern "C" void kernel_launch(void* const* d_in, const int* in_sizes, int n_in,
                              void* d_out, int out_size) {
    const float* x     = (const float*)d_in[0];
    const float* tw    = (const float*)d_in[1];
    const float* tb    = (const float*)d_in[2];
    const float* sw    = (const float*)d_in[3];
    const float* sb    = (const float*)d_in[4];
    const float* slw   = (const float*)d_in[5];
    const float* slb   = (const float*)d_in[6];
    const float* cheby = (const float*)d_in[7];
    const float* hw1   = (const float*)d_in[8];
    const float* hb1   = (const float*)d_in[9];
    const float* hw2   = (const float*)d_in[10];
    const float* hb2   = (const float*)d_in[11];
    const float* amp_w = (const float*)d_in[12];
    const float* amp_b = (const float*)d_in[13];
    const float* wav_w = (const float*)d_in[14];
    const float* gamma = (const float*)d_in[15];
    const float* beta  = (const float*)d_in[16];
    float* out = (float*)d_out;

    cudaFuncSetAttribute(gemm_kernel, cudaFuncAttributeMaxDynamicSharedMemorySize, SMEM_GEMM);

    prep_all<<<2049, 256>>>(cheby, wav_w, amp_w);
    decomp_kernel<<<(SEG*Bdim*Cdim)/256, 256>>>(x, tw, tb, sw, sb);   // 1024 blocks
    hyper_pool<<<Bdim, 512>>>(slw, slb);
    hyper_mm<<<dim3(4, Bdim, 8), 256>>>(hw1);
    hyper_psi<<<Bdim, 256>>>(hw2, hb2, hb1);
    gemm_kernel<<<296, 256, SMEM_GEMM>>>(amp_b);    // unified persistent GEMM
    epilogue_kernel<<<Mrows/2, 256>>>(x, gamma, beta, out);
}